// round 1
// baseline (speedup 1.0000x reference)
#include <cuda_runtime.h>
#include <cuda_bf16.h>
#include <math.h>

// Problem constants
#define B_  2
#define T_  1024
#define S_  2048
#define D_  1024
#define H_  16
#define HD_ 64
#define SCALE_ 0.125f   // 64^-0.5
#define RMS_EPS_ 1e-6f

// Scratch (device globals; no allocation allowed)
__device__ float g_q[B_ * T_ * D_];     // [B,T,D] (head-split view [B,T,H,HD])
__device__ float g_k[B_ * S_ * D_];
__device__ float g_v[B_ * S_ * D_];
__device__ float g_att[B_ * T_ * D_];   // attention output, [B,T,D]
__device__ float g_proj[B_ * T_ * D_];  // attn @ Wo^T

// ---------------------------------------------------------------------------
// SGEMM: C[M,N] = A[M,K] * W[N,K]^T   (both K-contiguous / row-major)
// 64x64 tile, BK=16, 256 threads, 4x4 microtile per thread.
// M, N, K all divisible by 64/16 for our shapes.
// ---------------------------------------------------------------------------
#define BM 64
#define BN 64
#define BK 16
__global__ __launch_bounds__(256) void sgemm_xwT(
    const float* __restrict__ A, const float* __restrict__ W,
    float* __restrict__ C, int M, int N, int K)
{
    __shared__ float As[BK][BM];
    __shared__ float Ws[BK][BN];

    const int tid = threadIdx.x;
    const int bm = blockIdx.y * BM;
    const int bn = blockIdx.x * BN;
    const int tx = tid & 15;       // 0..15 -> N
    const int ty = tid >> 4;       // 0..15 -> M

    // loader mapping: 64 rows x 16 k-cols, float4 per thread, 256 threads -> 1 iter
    const int lr = tid >> 2;          // 0..63 row in tile
    const int lc = (tid & 3) * 4;     // 0,4,8,12 (k)

    float acc[4][4];
    #pragma unroll
    for (int i = 0; i < 4; i++)
        #pragma unroll
        for (int j = 0; j < 4; j++) acc[i][j] = 0.f;

    for (int k0 = 0; k0 < K; k0 += BK) {
        float4 av = *(const float4*)&A[(size_t)(bm + lr) * K + k0 + lc];
        float4 wv = *(const float4*)&W[(size_t)(bn + lr) * K + k0 + lc];
        As[lc + 0][lr] = av.x; As[lc + 1][lr] = av.y;
        As[lc + 2][lr] = av.z; As[lc + 3][lr] = av.w;
        Ws[lc + 0][lr] = wv.x; Ws[lc + 1][lr] = wv.y;
        Ws[lc + 2][lr] = wv.z; Ws[lc + 3][lr] = wv.w;
        __syncthreads();

        #pragma unroll
        for (int kk = 0; kk < BK; kk++) {
            float a[4], b[4];
            #pragma unroll
            for (int i = 0; i < 4; i++) a[i] = As[kk][ty * 4 + i];
            #pragma unroll
            for (int j = 0; j < 4; j++) b[j] = Ws[kk][tx * 4 + j];
            #pragma unroll
            for (int i = 0; i < 4; i++)
                #pragma unroll
                for (int j = 0; j < 4; j++)
                    acc[i][j] += a[i] * b[j];
        }
        __syncthreads();
    }

    #pragma unroll
    for (int i = 0; i < 4; i++) {
        float4 r = make_float4(acc[i][0], acc[i][1], acc[i][2], acc[i][3]);
        *(float4*)&C[(size_t)(bm + ty * 4 + i) * N + bn + tx * 4] = r;
    }
}

// ---------------------------------------------------------------------------
// Flash attention with ALiBi bias (fp32, online softmax).
// grid: (T/128, H, B), block: 128 threads; thread = one query row.
// q/k/v are [B,L,D] with head-split columns [h*64 .. h*64+63].
// ---------------------------------------------------------------------------
#define ROWS 128
#define STILE 64
__global__ __launch_bounds__(ROWS) void attn_kernel(
    const float* __restrict__ q, const float* __restrict__ k,
    const float* __restrict__ v, float* __restrict__ o)
{
    __shared__ float Ks[STILE][HD_];
    __shared__ float Vs[STILE][HD_];

    const int b = blockIdx.z;
    const int h = blockIdx.y;
    const int t = blockIdx.x * ROWS + threadIdx.x;

    const float slope = exp2f(-(float)(h + 1) / 16.0f);

    // load q row into registers
    float qr[HD_];
    const float* qrow = q + ((size_t)(b * T_ + t)) * D_ + h * HD_;
    #pragma unroll
    for (int i = 0; i < HD_ / 4; i++) {
        float4 v4 = *(const float4*)(qrow + 4 * i);
        qr[4 * i + 0] = v4.x; qr[4 * i + 1] = v4.y;
        qr[4 * i + 2] = v4.z; qr[4 * i + 3] = v4.w;
    }

    float acc[HD_];
    #pragma unroll
    for (int d = 0; d < HD_; d++) acc[d] = 0.f;
    float m = -INFINITY, l = 0.f;

    const float tf = (float)t;

    for (int s0 = 0; s0 < S_; s0 += STILE) {
        // cooperative tile load: 64 rows x 16 float4 = 1024 float4, 128 threads
        #pragma unroll
        for (int it = 0; it < 8; it++) {
            int idx = it * ROWS + threadIdx.x;
            int r = idx >> 4;
            int c = (idx & 15) * 4;
            size_t gofs = ((size_t)(b * S_ + s0 + r)) * D_ + h * HD_ + c;
            *(float4*)&Ks[r][c] = *(const float4*)&k[gofs];
            *(float4*)&Vs[r][c] = *(const float4*)&v[gofs];
        }
        __syncthreads();

        float sreg[STILE];
        float tmax = -INFINITY;
        #pragma unroll 4
        for (int s = 0; s < STILE; s++) {
            float sc = 0.f;
            #pragma unroll
            for (int d = 0; d < HD_; d++) sc += qr[d] * Ks[s][d];
            sc = sc * SCALE_ - slope * fabsf(tf - (float)(s0 + s));
            sreg[s] = sc;
            tmax = fmaxf(tmax, sc);
        }

        float mnew = fmaxf(m, tmax);
        float corr = __expf(m - mnew);   // m=-inf first iter -> 0
        l *= corr;
        #pragma unroll
        for (int d = 0; d < HD_; d++) acc[d] *= corr;

        #pragma unroll 2
        for (int s = 0; s < STILE; s++) {
            float p = __expf(sreg[s] - mnew);
            l += p;
            #pragma unroll
            for (int d = 0; d < HD_; d++) acc[d] += p * Vs[s][d];
        }
        m = mnew;
        __syncthreads();
    }

    const float inv = 1.f / l;
    float* orow = o + ((size_t)(b * T_ + t)) * D_ + h * HD_;
    #pragma unroll
    for (int i = 0; i < HD_ / 4; i++) {
        float4 r = make_float4(acc[4 * i] * inv, acc[4 * i + 1] * inv,
                               acc[4 * i + 2] * inv, acc[4 * i + 3] * inv);
        *(float4*)(orow + 4 * i) = r;
    }
}

// ---------------------------------------------------------------------------
// residual + RMSNorm: out = (query + proj) * rsqrt(mean((q+p)^2) + eps) * w
// grid: B*T blocks, 256 threads, 4 elems/thread.
// ---------------------------------------------------------------------------
__global__ __launch_bounds__(256) void rms_kernel(
    const float* __restrict__ query, const float* __restrict__ proj,
    const float* __restrict__ w, float* __restrict__ out)
{
    __shared__ float sh[8];
    __shared__ float s_inv;
    const size_t row = blockIdx.x;
    const float* qr = query + row * D_;
    const float* pr = proj + row * D_;
    float* orow = out + row * D_;

    float x[4];
    float ss = 0.f;
    #pragma unroll
    for (int i = 0; i < 4; i++) {
        int idx = threadIdx.x + i * 256;
        x[i] = qr[idx] + pr[idx];
        ss += x[i] * x[i];
    }
    // warp reduce
    #pragma unroll
    for (int ofs = 16; ofs > 0; ofs >>= 1)
        ss += __shfl_xor_sync(0xffffffffu, ss, ofs);
    const int lane = threadIdx.x & 31, wid = threadIdx.x >> 5;
    if (lane == 0) sh[wid] = ss;
    __syncthreads();
    if (threadIdx.x == 0) {
        float tot = 0.f;
        #pragma unroll
        for (int i = 0; i < 8; i++) tot += sh[i];
        s_inv = rsqrtf(tot * (1.0f / D_) + RMS_EPS_);
    }
    __syncthreads();
    const float inv = s_inv;
    #pragma unroll
    for (int i = 0; i < 4; i++) {
        int idx = threadIdx.x + i * 256;
        orow[idx] = x[i] * inv * w[idx];
    }
}

// ---------------------------------------------------------------------------
extern "C" void kernel_launch(void* const* d_in, const int* in_sizes, int n_in,
                              void* d_out, int out_size)
{
    const float* query   = (const float*)d_in[0];
    const float* context = (const float*)d_in[1];
    const float* Wq      = (const float*)d_in[2];
    const float* Wk      = (const float*)d_in[3];
    const float* Wv      = (const float*)d_in[4];
    const float* Wo      = (const float*)d_in[5];
    const float* rmsw    = (const float*)d_in[6];
    float* out = (float*)d_out;

    float *pq, *pk, *pv, *patt, *pproj;
    cudaGetSymbolAddress((void**)&pq,    g_q);
    cudaGetSymbolAddress((void**)&pk,    g_k);
    cudaGetSymbolAddress((void**)&pv,    g_v);
    cudaGetSymbolAddress((void**)&patt,  g_att);
    cudaGetSymbolAddress((void**)&pproj, g_proj);

    const int MQ = B_ * T_;   // 2048
    const int MK = B_ * S_;   // 4096

    dim3 gq(D_ / BN, MQ / BM);   // 16 x 32
    dim3 gk(D_ / BN, MK / BM);   // 16 x 64

    sgemm_xwT<<<gq, 256>>>(query,   Wq, pq, MQ, D_, D_);
    sgemm_xwT<<<gk, 256>>>(context, Wk, pk, MK, D_, D_);
    sgemm_xwT<<<gk, 256>>>(context, Wv, pv, MK, D_, D_);

    attn_kernel<<<dim3(T_ / ROWS, H_, B_), ROWS>>>(pq, pk, pv, patt);

    sgemm_xwT<<<gq, 256>>>(patt, Wo, pproj, MQ, D_, D_);

    rms_kernel<<<MQ, 256>>>(query, pproj, rmsw, out);
}

// round 2
// speedup vs baseline: 1.1248x; 1.1248x over previous
#include <cuda_runtime.h>
#include <cuda_bf16.h>
#include <math.h>

// Problem constants
#define B_  2
#define T_  1024
#define S_  2048
#define D_  1024
#define H_  16
#define HD_ 64
#define SCALE_ 0.125f   // 64^-0.5
#define RMS_EPS_ 1e-6f

// Scratch (device globals; no allocation allowed)
__device__ float g_q[B_ * T_ * D_];
__device__ float g_k[B_ * S_ * D_];
__device__ float g_v[B_ * S_ * D_];
__device__ float g_att[B_ * T_ * D_];
__device__ float g_proj[B_ * T_ * D_];

// ---------------------------------------------------------------------------
// SGEMM: C[M,N] = A[M,K] * W[N,K]^T  (both row-major, K contiguous)
// 128x128 tile, BK=16, 256 threads, 8x8 microtile, register-prefetch
// double buffering of the global loads.
// ---------------------------------------------------------------------------
#define GBM 128
#define GBN 128
#define GBK 16
__global__ __launch_bounds__(256) void sgemm_xwT(
    const float* __restrict__ A, const float* __restrict__ W,
    float* __restrict__ C, int M, int N, int K)
{
    __shared__ float As[GBK][GBM];
    __shared__ float Ws[GBK][GBN];

    const int tid = threadIdx.x;
    const int bm = blockIdx.y * GBM;
    const int bn = blockIdx.x * GBN;
    const int ty = tid >> 4;      // 0..15 -> M groups of 8
    const int tx = tid & 15;      // 0..15 -> N groups of 8

    // loader: each thread fetches 8 consecutive k-floats of one row (2x float4)
    const int lr = tid >> 1;          // 0..127
    const int lc = (tid & 1) * 8;     // 0 or 8

    const float* Ag = A + (size_t)(bm + lr) * K + lc;
    const float* Wg = W + (size_t)(bn + lr) * K + lc;

    float4 pa0 = *(const float4*)(Ag + 0);
    float4 pa1 = *(const float4*)(Ag + 4);
    float4 pw0 = *(const float4*)(Wg + 0);
    float4 pw1 = *(const float4*)(Wg + 4);

    float acc[8][8];
    #pragma unroll
    for (int i = 0; i < 8; i++)
        #pragma unroll
        for (int j = 0; j < 8; j++) acc[i][j] = 0.f;

    for (int k0 = 0; k0 < K; k0 += GBK) {
        // commit prefetched tile to smem (k-major layout for contiguous frags)
        As[lc + 0][lr] = pa0.x; As[lc + 1][lr] = pa0.y;
        As[lc + 2][lr] = pa0.z; As[lc + 3][lr] = pa0.w;
        As[lc + 4][lr] = pa1.x; As[lc + 5][lr] = pa1.y;
        As[lc + 6][lr] = pa1.z; As[lc + 7][lr] = pa1.w;
        Ws[lc + 0][lr] = pw0.x; Ws[lc + 1][lr] = pw0.y;
        Ws[lc + 2][lr] = pw0.z; Ws[lc + 3][lr] = pw0.w;
        Ws[lc + 4][lr] = pw1.x; Ws[lc + 5][lr] = pw1.y;
        Ws[lc + 6][lr] = pw1.z; Ws[lc + 7][lr] = pw1.w;
        __syncthreads();

        // prefetch next tile while computing this one
        if (k0 + GBK < K) {
            pa0 = *(const float4*)(Ag + k0 + GBK + 0);
            pa1 = *(const float4*)(Ag + k0 + GBK + 4);
            pw0 = *(const float4*)(Wg + k0 + GBK + 0);
            pw1 = *(const float4*)(Wg + k0 + GBK + 4);
        }

        #pragma unroll
        for (int kk = 0; kk < GBK; kk++) {
            float4 a0 = *(const float4*)&As[kk][ty * 8];
            float4 a1 = *(const float4*)&As[kk][ty * 8 + 4];
            float4 b0 = *(const float4*)&Ws[kk][tx * 8];
            float4 b1 = *(const float4*)&Ws[kk][tx * 8 + 4];
            float a[8] = {a0.x, a0.y, a0.z, a0.w, a1.x, a1.y, a1.z, a1.w};
            float b[8] = {b0.x, b0.y, b0.z, b0.w, b1.x, b1.y, b1.z, b1.w};
            #pragma unroll
            for (int i = 0; i < 8; i++)
                #pragma unroll
                for (int j = 0; j < 8; j++)
                    acc[i][j] += a[i] * b[j];
        }
        __syncthreads();
    }

    #pragma unroll
    for (int i = 0; i < 8; i++) {
        float* crow = &C[(size_t)(bm + ty * 8 + i) * N + bn + tx * 8];
        *(float4*)(crow + 0) = make_float4(acc[i][0], acc[i][1], acc[i][2], acc[i][3]);
        *(float4*)(crow + 4) = make_float4(acc[i][4], acc[i][5], acc[i][6], acc[i][7]);
    }
}

// ---------------------------------------------------------------------------
// Flash attention with ALiBi bias (fp32, online softmax).
// grid: (T/128, H, B), block: 128 threads; thread = one query row.
// Vectorized float4 smem reads; scores chunked by 16 to cap registers.
// ---------------------------------------------------------------------------
#define ROWS 128
#define STILE 64
#define CH 16
__global__ __launch_bounds__(ROWS) void attn_kernel(
    const float* __restrict__ q, const float* __restrict__ k,
    const float* __restrict__ v, float* __restrict__ o)
{
    __shared__ float Ks[STILE][HD_];
    __shared__ float Vs[STILE][HD_];

    const int b = blockIdx.z;
    const int h = blockIdx.y;
    const int t = blockIdx.x * ROWS + threadIdx.x;

    const float slope = exp2f(-(float)(h + 1) / 16.0f);

    float qr[HD_];
    const float* qrow = q + ((size_t)(b * T_ + t)) * D_ + h * HD_;
    #pragma unroll
    for (int i = 0; i < HD_ / 4; i++) {
        float4 v4 = *(const float4*)(qrow + 4 * i);
        qr[4 * i + 0] = v4.x; qr[4 * i + 1] = v4.y;
        qr[4 * i + 2] = v4.z; qr[4 * i + 3] = v4.w;
    }

    float acc[HD_];
    #pragma unroll
    for (int d = 0; d < HD_; d++) acc[d] = 0.f;
    float m = -INFINITY, l = 0.f;

    const float tf = (float)t;

    for (int s0 = 0; s0 < S_; s0 += STILE) {
        // cooperative tile load: 64 rows x 16 float4 each for K and V
        #pragma unroll
        for (int it = 0; it < 8; it++) {
            int idx = it * ROWS + threadIdx.x;
            int r = idx >> 4;
            int c = (idx & 15) * 4;
            size_t gofs = ((size_t)(b * S_ + s0 + r)) * D_ + h * HD_ + c;
            *(float4*)&Ks[r][c] = *(const float4*)&k[gofs];
            *(float4*)&Vs[r][c] = *(const float4*)&v[gofs];
        }
        __syncthreads();

        #pragma unroll 1
        for (int c0 = 0; c0 < STILE; c0 += CH) {
            float sreg[CH];
            float tmax = -INFINITY;
            #pragma unroll
            for (int j = 0; j < CH; j++) {
                const int s = c0 + j;
                const float4* kr = (const float4*)Ks[s];
                float sc = 0.f;
                #pragma unroll
                for (int i = 0; i < HD_ / 4; i++) {
                    float4 kv = kr[i];
                    sc += qr[4 * i + 0] * kv.x + qr[4 * i + 1] * kv.y
                        + qr[4 * i + 2] * kv.z + qr[4 * i + 3] * kv.w;
                }
                sc = sc * SCALE_ - slope * fabsf(tf - (float)(s0 + s));
                sreg[j] = sc;
                tmax = fmaxf(tmax, sc);
            }

            float mnew = fmaxf(m, tmax);
            float corr = __expf(m - mnew);   // m=-inf first iter -> 0
            l *= corr;
            #pragma unroll
            for (int d = 0; d < HD_; d++) acc[d] *= corr;

            #pragma unroll
            for (int j = 0; j < CH; j++) {
                const int s = c0 + j;
                float p = __expf(sreg[j] - mnew);
                l += p;
                const float4* vr = (const float4*)Vs[s];
                #pragma unroll
                for (int i = 0; i < HD_ / 4; i++) {
                    float4 vv = vr[i];
                    acc[4 * i + 0] += p * vv.x;
                    acc[4 * i + 1] += p * vv.y;
                    acc[4 * i + 2] += p * vv.z;
                    acc[4 * i + 3] += p * vv.w;
                }
            }
            m = mnew;
        }
        __syncthreads();
    }

    const float inv = 1.f / l;
    float* orow = o + ((size_t)(b * T_ + t)) * D_ + h * HD_;
    #pragma unroll
    for (int i = 0; i < HD_ / 4; i++) {
        float4 r = make_float4(acc[4 * i] * inv, acc[4 * i + 1] * inv,
                               acc[4 * i + 2] * inv, acc[4 * i + 3] * inv);
        *(float4*)(orow + 4 * i) = r;
    }
}

// ---------------------------------------------------------------------------
// residual + RMSNorm
// ---------------------------------------------------------------------------
__global__ __launch_bounds__(256) void rms_kernel(
    const float* __restrict__ query, const float* __restrict__ proj,
    const float* __restrict__ w, float* __restrict__ out)
{
    __shared__ float sh[8];
    __shared__ float s_inv;
    const size_t row = blockIdx.x;
    const float* qr = query + row * D_;
    const float* pr = proj + row * D_;
    float* orow = out + row * D_;

    float x[4];
    float ss = 0.f;
    #pragma unroll
    for (int i = 0; i < 4; i++) {
        int idx = threadIdx.x + i * 256;
        x[i] = qr[idx] + pr[idx];
        ss += x[i] * x[i];
    }
    #pragma unroll
    for (int ofs = 16; ofs > 0; ofs >>= 1)
        ss += __shfl_xor_sync(0xffffffffu, ss, ofs);
    const int lane = threadIdx.x & 31, wid = threadIdx.x >> 5;
    if (lane == 0) sh[wid] = ss;
    __syncthreads();
    if (threadIdx.x == 0) {
        float tot = 0.f;
        #pragma unroll
        for (int i = 0; i < 8; i++) tot += sh[i];
        s_inv = rsqrtf(tot * (1.0f / D_) + RMS_EPS_);
    }
    __syncthreads();
    const float inv = s_inv;
    #pragma unroll
    for (int i = 0; i < 4; i++) {
        int idx = threadIdx.x + i * 256;
        orow[idx] = x[i] * inv * w[idx];
    }
}

// ---------------------------------------------------------------------------
extern "C" void kernel_launch(void* const* d_in, const int* in_sizes, int n_in,
                              void* d_out, int out_size)
{
    const float* query   = (const float*)d_in[0];
    const float* context = (const float*)d_in[1];
    const float* Wq      = (const float*)d_in[2];
    const float* Wk      = (const float*)d_in[3];
    const float* Wv      = (const float*)d_in[4];
    const float* Wo      = (const float*)d_in[5];
    const float* rmsw    = (const float*)d_in[6];
    float* out = (float*)d_out;

    float *pq, *pk, *pv, *patt, *pproj;
    cudaGetSymbolAddress((void**)&pq,    g_q);
    cudaGetSymbolAddress((void**)&pk,    g_k);
    cudaGetSymbolAddress((void**)&pv,    g_v);
    cudaGetSymbolAddress((void**)&patt,  g_att);
    cudaGetSymbolAddress((void**)&pproj, g_proj);

    const int MQ = B_ * T_;   // 2048
    const int MK = B_ * S_;   // 4096

    dim3 gq(D_ / GBN, MQ / GBM);   // 8 x 16
    dim3 gk(D_ / GBN, MK / GBM);   // 8 x 32

    sgemm_xwT<<<gq, 256>>>(query,   Wq, pq, MQ, D_, D_);
    sgemm_xwT<<<gk, 256>>>(context, Wk, pk, MK, D_, D_);
    sgemm_xwT<<<gk, 256>>>(context, Wv, pv, MK, D_, D_);

    attn_kernel<<<dim3(T_ / ROWS, H_, B_), ROWS>>>(pq, pk, pv, patt);

    sgemm_xwT<<<gq, 256>>>(patt, Wo, pproj, MQ, D_, D_);

    rms_kernel<<<MQ, 256>>>(query, pproj, rmsw, out);
}

// round 6
// speedup vs baseline: 1.2850x; 1.1423x over previous
#include <cuda_runtime.h>
#include <cuda_bf16.h>
#include <math.h>

// Problem constants
#define B_  2
#define T_  1024
#define S_  2048
#define D_  1024
#define H_  16
#define HD_ 64
#define SCALE_ 0.125f   // 64^-0.5
#define RMS_EPS_ 1e-6f

#define NS_ 2              // key-range splits for attention
#define SPS (S_ / NS_)     // keys per split = 1024

// Scratch (device globals; no allocation allowed)
__device__ float g_q[B_ * T_ * D_];
__device__ float g_k[B_ * S_ * D_];
__device__ float g_v[B_ * S_ * D_];
__device__ float g_att[B_ * T_ * D_];
__device__ float g_proj[B_ * T_ * D_];
// attention partials: [NS][B][H][T] x (acc 64 | m | l)
__device__ float g_pacc[NS_ * B_ * H_ * T_ * HD_];
__device__ float g_pm[NS_ * B_ * H_ * T_];
__device__ float g_pl[NS_ * B_ * H_ * T_];

// ---------------------------------------------------------------------------
// SGEMM: C[M,N] = A[M,K] * W[N,K]^T  (row-major, K contiguous)
// 128x128 tile, BK=16, 256 threads, 8x8 microtile, reg-prefetch double buffer.
// ---------------------------------------------------------------------------
#define GBM 128
#define GBN 128
#define GBK 16
__global__ __launch_bounds__(256) void sgemm_xwT(
    const float* __restrict__ A, const float* __restrict__ W,
    float* __restrict__ C, int M, int N, int K)
{
    __shared__ float As[GBK][GBM];
    __shared__ float Ws[GBK][GBN];

    const int tid = threadIdx.x;
    const int bm = blockIdx.y * GBM;
    const int bn = blockIdx.x * GBN;
    const int ty = tid >> 4;
    const int tx = tid & 15;

    const int lr = tid >> 1;
    const int lc = (tid & 1) * 8;

    const float* Ag = A + (size_t)(bm + lr) * K + lc;
    const float* Wg = W + (size_t)(bn + lr) * K + lc;

    float4 pa0 = *(const float4*)(Ag + 0);
    float4 pa1 = *(const float4*)(Ag + 4);
    float4 pw0 = *(const float4*)(Wg + 0);
    float4 pw1 = *(const float4*)(Wg + 4);

    float acc[8][8];
    #pragma unroll
    for (int i = 0; i < 8; i++)
        #pragma unroll
        for (int j = 0; j < 8; j++) acc[i][j] = 0.f;

    for (int k0 = 0; k0 < K; k0 += GBK) {
        As[lc + 0][lr] = pa0.x; As[lc + 1][lr] = pa0.y;
        As[lc + 2][lr] = pa0.z; As[lc + 3][lr] = pa0.w;
        As[lc + 4][lr] = pa1.x; As[lc + 5][lr] = pa1.y;
        As[lc + 6][lr] = pa1.z; As[lc + 7][lr] = pa1.w;
        Ws[lc + 0][lr] = pw0.x; Ws[lc + 1][lr] = pw0.y;
        Ws[lc + 2][lr] = pw0.z; Ws[lc + 3][lr] = pw0.w;
        Ws[lc + 4][lr] = pw1.x; Ws[lc + 5][lr] = pw1.y;
        Ws[lc + 6][lr] = pw1.z; Ws[lc + 7][lr] = pw1.w;
        __syncthreads();

        if (k0 + GBK < K) {
            pa0 = *(const float4*)(Ag + k0 + GBK + 0);
            pa1 = *(const float4*)(Ag + k0 + GBK + 4);
            pw0 = *(const float4*)(Wg + k0 + GBK + 0);
            pw1 = *(const float4*)(Wg + k0 + GBK + 4);
        }

        #pragma unroll
        for (int kk = 0; kk < GBK; kk++) {
            float4 a0 = *(const float4*)&As[kk][ty * 8];
            float4 a1 = *(const float4*)&As[kk][ty * 8 + 4];
            float4 b0 = *(const float4*)&Ws[kk][tx * 8];
            float4 b1 = *(const float4*)&Ws[kk][tx * 8 + 4];
            float a[8] = {a0.x, a0.y, a0.z, a0.w, a1.x, a1.y, a1.z, a1.w};
            float b[8] = {b0.x, b0.y, b0.z, b0.w, b1.x, b1.y, b1.z, b1.w};
            #pragma unroll
            for (int i = 0; i < 8; i++)
                #pragma unroll
                for (int j = 0; j < 8; j++)
                    acc[i][j] += a[i] * b[j];
        }
        __syncthreads();
    }

    #pragma unroll
    for (int i = 0; i < 8; i++) {
        float* crow = &C[(size_t)(bm + ty * 8 + i) * N + bn + tx * 8];
        *(float4*)(crow + 0) = make_float4(acc[i][0], acc[i][1], acc[i][2], acc[i][3]);
        *(float4*)(crow + 4) = make_float4(acc[i][4], acc[i][5], acc[i][6], acc[i][7]);
    }
}

// ---------------------------------------------------------------------------
// Flash attention partials with ALiBi (fp32, online softmax), split-KV.
// Block: 128 threads; lane = (r 0..15, half 0..1); warp = 16 rows x 2 halves.
// Block covers 64 query rows, one split of the key range.
// grid: (T/64, NS, H*B)
// ---------------------------------------------------------------------------
#define AROWS 64
#define STILE 64
#define CH 16
#define HHD 32   // half head dim
__global__ __launch_bounds__(128) void attn_partial_kernel(
    const float* __restrict__ q, const float* __restrict__ k,
    const float* __restrict__ v)
{
    __shared__ float Ks[STILE][HD_];
    __shared__ float Vs[STILE][HD_];

    const int hb   = blockIdx.z;         // h*B? -> decode: z = b*H_+h
    const int b    = hb / H_;
    const int h    = hb % H_;
    const int split= blockIdx.y;
    const int wid  = threadIdx.x >> 5;
    const int lane = threadIdx.x & 31;
    const int r    = lane & 15;
    const int half = lane >> 4;

    const int t = blockIdx.x * AROWS + wid * 16 + r;
    const float slope = exp2f(-(float)(h + 1) / 16.0f);
    const float tf = (float)t;

    // load my half of the q row
    float qr[HHD];
    const float* qrow = q + ((size_t)(b * T_ + t)) * D_ + h * HD_ + half * HHD;
    #pragma unroll
    for (int i = 0; i < HHD / 4; i++) {
        float4 v4 = *(const float4*)(qrow + 4 * i);
        qr[4 * i + 0] = v4.x; qr[4 * i + 1] = v4.y;
        qr[4 * i + 2] = v4.z; qr[4 * i + 3] = v4.w;
    }

    float acc[HHD];
    #pragma unroll
    for (int d = 0; d < HHD; d++) acc[d] = 0.f;
    float m = -INFINITY, l = 0.f;

    const int sbeg = split * SPS;
    const int send = sbeg + SPS;

    for (int s0 = sbeg; s0 < send; s0 += STILE) {
        // cooperative tile load: 64 rows x 16 float4 each, 128 threads -> 8 iters
        #pragma unroll
        for (int it = 0; it < 8; it++) {
            int idx = it * 128 + threadIdx.x;
            int rr = idx >> 4;
            int cc = (idx & 15) * 4;
            size_t gofs = ((size_t)(b * S_ + s0 + rr)) * D_ + h * HD_ + cc;
            *(float4*)&Ks[rr][cc] = *(const float4*)&k[gofs];
            *(float4*)&Vs[rr][cc] = *(const float4*)&v[gofs];
        }
        __syncthreads();

        #pragma unroll 1
        for (int c0 = 0; c0 < STILE; c0 += CH) {
            float sreg[CH];
            float tmax = -INFINITY;
            #pragma unroll
            for (int j = 0; j < CH; j++) {
                const int s = c0 + j;
                const float4* kr = (const float4*)&Ks[s][half * HHD];
                float sc = 0.f;
                #pragma unroll
                for (int i = 0; i < HHD / 4; i++) {
                    float4 kv = kr[i];
                    sc += qr[4 * i + 0] * kv.x + qr[4 * i + 1] * kv.y
                        + qr[4 * i + 2] * kv.z + qr[4 * i + 3] * kv.w;
                }
                // combine the two halves of the dot product
                sc += __shfl_xor_sync(0xffffffffu, sc, 16);
                sc = sc * SCALE_ - slope * fabsf(tf - (float)(s0 + s));
                sreg[j] = sc;
                tmax = fmaxf(tmax, sc);
            }

            float mnew = fmaxf(m, tmax);
            float corr = __expf(m - mnew);
            l *= corr;
            #pragma unroll
            for (int d = 0; d < HHD; d++) acc[d] *= corr;

            #pragma unroll
            for (int j = 0; j < CH; j++) {
                const int s = c0 + j;
                float p = __expf(sreg[j] - mnew);
                l += p;
                const float4* vr = (const float4*)&Vs[s][half * HHD];
                #pragma unroll
                for (int i = 0; i < HHD / 4; i++) {
                    float4 vv = vr[i];
                    acc[4 * i + 0] += p * vv.x;
                    acc[4 * i + 1] += p * vv.y;
                    acc[4 * i + 2] += p * vv.z;
                    acc[4 * i + 3] += p * vv.w;
                }
            }
            m = mnew;
        }
        __syncthreads();
    }

    // write partials: index (split, b, h, t)
    const size_t pidx = (((size_t)split * B_ + b) * H_ + h) * T_ + t;
    float* pacc = g_pacc + pidx * HD_ + half * HHD;
    #pragma unroll
    for (int i = 0; i < HHD / 4; i++) {
        *(float4*)(pacc + 4 * i) =
            make_float4(acc[4 * i], acc[4 * i + 1], acc[4 * i + 2], acc[4 * i + 3]);
    }
    if (half == 0) {
        g_pm[pidx] = m;
        g_pl[pidx] = l;
    }
}

// ---------------------------------------------------------------------------
// Combine split-KV partials -> attention output [B,T,D] at g_att.
// Block: 256 threads = 4 rows x 64 dims. grid = B*H*T/4.
// ---------------------------------------------------------------------------
__global__ __launch_bounds__(256) void attn_combine_kernel(float* __restrict__ o)
{
    const int d = threadIdx.x & 63;
    const int rlocal = threadIdx.x >> 6;
    const size_t row = (size_t)blockIdx.x * 4 + rlocal;  // (b*H + h)*T + t
    const int t = row % T_;
    const int h = (row / T_) % H_;
    const int b = row / ((size_t)T_ * H_);

    float m0 = g_pm[row];
    float l0 = g_pl[row];
    float m1 = g_pm[(size_t)B_ * H_ * T_ + row];
    float l1 = g_pl[(size_t)B_ * H_ * T_ + row];

    float M = fmaxf(m0, m1);
    float e0 = __expf(m0 - M), e1 = __expf(m1 - M);
    float L = l0 * e0 + l1 * e1;
    float inv = 1.f / L;

    float a0 = g_pacc[row * HD_ + d];
    float a1 = g_pacc[((size_t)B_ * H_ * T_ + row) * HD_ + d];
    float val = (a0 * e0 + a1 * e1) * inv;

    o[((size_t)(b * T_ + t)) * D_ + h * HD_ + d] = val;
}

// ---------------------------------------------------------------------------
// residual + RMSNorm
// ---------------------------------------------------------------------------
__global__ __launch_bounds__(256) void rms_kernel(
    const float* __restrict__ query, const float* __restrict__ proj,
    const float* __restrict__ w, float* __restrict__ out)
{
    __shared__ float sh[8];
    __shared__ float s_inv;
    const size_t row = blockIdx.x;
    const float* qr = query + row * D_;
    const float* pr = proj + row * D_;
    float* orow = out + row * D_;

    float x[4];
    float ss = 0.f;
    #pragma unroll
    for (int i = 0; i < 4; i++) {
        int idx = threadIdx.x + i * 256;
        x[i] = qr[idx] + pr[idx];
        ss += x[i] * x[i];
    }
    #pragma unroll
    for (int ofs = 16; ofs > 0; ofs >>= 1)
        ss += __shfl_xor_sync(0xffffffffu, ss, ofs);
    const int lane = threadIdx.x & 31, wid = threadIdx.x >> 5;
    if (lane == 0) sh[wid] = ss;
    __syncthreads();
    if (threadIdx.x == 0) {
        float tot = 0.f;
        #pragma unroll
        for (int i = 0; i < 8; i++) tot += sh[i];
        s_inv = rsqrtf(tot * (1.0f / D_) + RMS_EPS_);
    }
    __syncthreads();
    const float inv = s_inv;
    #pragma unroll
    for (int i = 0; i < 4; i++) {
        int idx = threadIdx.x + i * 256;
        orow[idx] = x[i] * inv * w[idx];
    }
}

// ---------------------------------------------------------------------------
extern "C" void kernel_launch(void* const* d_in, const int* in_sizes, int n_in,
                              void* d_out, int out_size)
{
    const float* query   = (const float*)d_in[0];
    const float* context = (const float*)d_in[1];
    const float* Wq      = (const float*)d_in[2];
    const float* Wk      = (const float*)d_in[3];
    const float* Wv      = (const float*)d_in[4];
    const float* Wo      = (const float*)d_in[5];
    const float* rmsw    = (const float*)d_in[6];
    float* out = (float*)d_out;

    float *pq, *pk, *pv, *patt, *pproj;
    cudaGetSymbolAddress((void**)&pq,    g_q);
    cudaGetSymbolAddress((void**)&pk,    g_k);
    cudaGetSymbolAddress((void**)&pv,    g_v);
    cudaGetSymbolAddress((void**)&patt,  g_att);
    cudaGetSymbolAddress((void**)&pproj, g_proj);

    const int MQ = B_ * T_;   // 2048
    const int MK = B_ * S_;   // 4096

    dim3 gq(D_ / GBN, MQ / GBM);
    dim3 gk(D_ / GBN, MK / GBM);

    sgemm_xwT<<<gq, 256>>>(query,   Wq, pq, MQ, D_, D_);
    sgemm_xwT<<<gk, 256>>>(context, Wk, pk, MK, D_, D_);
    sgemm_xwT<<<gk, 256>>>(context, Wv, pv, MK, D_, D_);

    attn_partial_kernel<<<dim3(T_ / AROWS, NS_, B_ * H_), 128>>>(pq, pk, pv);
    attn_combine_kernel<<<(B_ * H_ * T_) / 4, 256>>>(patt);

    sgemm_xwT<<<gq, 256>>>(patt, Wo, pproj, MQ, D_, D_);

    rms_kernel<<<MQ, 256>>>(query, pproj, rmsw, out);
}

// round 8
// speedup vs baseline: 1.6330x; 1.2709x over previous
#include <cuda_runtime.h>
#include <cuda_bf16.h>
#include <math.h>
#include <stdint.h>

// Problem constants
#define B_  2
#define T_  1024
#define S_  2048
#define D_  1024
#define H_  16
#define HD_ 64
#define SCALE_ 0.125f
#define RMS_EPS_ 1e-6f

#define NS_ 2
#define SPS (S_ / NS_)

// bf16-split GEMM config: K'' = [hi,hi,lo] x [hi,lo,hi]
#define KTOT (3 * D_)        // 3072
#define KB 32                // bf16 K per stage
#define NITER (KTOT / KB)    // 96
#define GTM 128
#define GTN 128
#define APITCH 40            // padded row pitch in bf16 (80 bytes)

// Scratch (device globals; no allocation allowed)
__device__ float g_q[B_ * T_ * D_];
__device__ float g_k[B_ * S_ * D_];
__device__ float g_v[B_ * S_ * D_];
__device__ float g_att[B_ * T_ * D_];
__device__ float g_proj[B_ * T_ * D_];
__device__ float g_pacc[NS_ * B_ * H_ * T_ * HD_];
__device__ float g_pm[NS_ * B_ * H_ * T_];
__device__ float g_pl[NS_ * B_ * H_ * T_];
// bf16 split operands
__device__ __nv_bfloat16 g_qs[(size_t)B_ * T_ * KTOT];
__device__ __nv_bfloat16 g_cs[(size_t)B_ * S_ * KTOT];
__device__ __nv_bfloat16 g_as[(size_t)B_ * T_ * KTOT];
__device__ __nv_bfloat16 g_wqs[(size_t)D_ * KTOT];
__device__ __nv_bfloat16 g_wks[(size_t)D_ * KTOT];
__device__ __nv_bfloat16 g_wvs[(size_t)D_ * KTOT];
__device__ __nv_bfloat16 g_wos[(size_t)D_ * KTOT];

// ============================ PTX helpers (base ISA only) ====================
__device__ __forceinline__ uint32_t smem_u32(const void* p) {
    uint32_t a;
    asm("{ .reg .u64 t; cvta.to.shared.u64 t, %1; cvt.u32.u64 %0, t; }"
        : "=r"(a) : "l"(p));
    return a;
}

#define CP_ASYNC16(dst_u32, src_ptr) \
    asm volatile("cp.async.cg.shared.global [%0], [%1], 16;" \
        :: "r"(dst_u32), "l"(src_ptr))
#define CP_COMMIT() asm volatile("cp.async.commit_group;" ::: "memory")
#define CP_WAIT1()  asm volatile("cp.async.wait_group 1;" ::: "memory")
#define CP_WAIT0()  asm volatile("cp.async.wait_group 0;" ::: "memory")

#define LDMATRIX_X4(r0, r1, r2, r3, addr) \
    asm volatile("ldmatrix.sync.aligned.m8n8.x4.shared.b16 {%0,%1,%2,%3}, [%4];" \
        : "=r"(r0), "=r"(r1), "=r"(r2), "=r"(r3) : "r"(addr))

#define MMA16816(d0, d1, d2, d3, a0, a1, a2, a3, b0, b1) \
    asm volatile("mma.sync.aligned.m16n8k16.row.col.f32.bf16.bf16.f32 " \
        "{%0,%1,%2,%3}, {%4,%5,%6,%7}, {%8,%9}, {%0,%1,%2,%3};" \
        : "+f"(d0), "+f"(d1), "+f"(d2), "+f"(d3) \
        : "r"(a0), "r"(a1), "r"(a2), "r"(a3), "r"(b0), "r"(b1))

// ---------------------------------------------------------------------------
// Split conversion kernels: fp32 [rows,1024] -> bf16 [rows,3072]
// act: [hi, hi, lo]    wgt: [hi, lo, hi]
// ---------------------------------------------------------------------------
__global__ __launch_bounds__(256) void split_act(
    const float* __restrict__ in, __nv_bfloat16* __restrict__ out)
{
    const size_t row = blockIdx.x;
    const float* r = in + row * D_;
    __nv_bfloat16* o = out + row * (size_t)KTOT;
    #pragma unroll
    for (int i = 0; i < 4; i++) {
        int c = threadIdx.x + i * 256;
        float x = r[c];
        __nv_bfloat16 hi = __float2bfloat16(x);
        __nv_bfloat16 lo = __float2bfloat16(x - __bfloat162float(hi));
        o[c] = hi; o[D_ + c] = hi; o[2 * D_ + c] = lo;
    }
}

__global__ __launch_bounds__(256) void split_wgt(
    const float* __restrict__ in, __nv_bfloat16* __restrict__ out)
{
    const size_t row = blockIdx.x;
    const float* r = in + row * D_;
    __nv_bfloat16* o = out + row * (size_t)KTOT;
    #pragma unroll
    for (int i = 0; i < 4; i++) {
        int c = threadIdx.x + i * 256;
        float x = r[c];
        __nv_bfloat16 hi = __float2bfloat16(x);
        __nv_bfloat16 lo = __float2bfloat16(x - __bfloat162float(hi));
        o[c] = hi; o[D_ + c] = lo; o[2 * D_ + c] = hi;
    }
}

// ---------------------------------------------------------------------------
// bf16 mma.sync GEMM: C[M,N](f32) = A''[M,KTOT] * W''[N,KTOT]^T
// Block 256 thr (8 warps, 4x2 grid; warp tile 32x64), tile 128x128xKB32.
// cp.async double-buffered smem; 80B-padded rows (bank-conflict-free ldmatrix).
// ---------------------------------------------------------------------------
__global__ __launch_bounds__(256) void gemm_bf16_mma(
    const __nv_bfloat16* __restrict__ A, const __nv_bfloat16* __restrict__ W,
    float* __restrict__ C, int N)
{
    __shared__ __align__(16) __nv_bfloat16 As[2][GTM * APITCH];
    __shared__ __align__(16) __nv_bfloat16 Bs[2][GTN * APITCH];

    const int tid = threadIdx.x;
    const int wid = tid >> 5;
    const int lane = tid & 31;
    const int wm = wid & 3;            // 0..3 -> M
    const int wn = wid >> 2;           // 0..1 -> N
    const int bm = blockIdx.y * GTM;
    const int bn = blockIdx.x * GTN;

    // loader mapping: thread -> (row, two 16B chunks)
    const int lrow = tid >> 1;                 // 0..127
    const int lch  = (tid & 1) * 2;            // 0 or 2 (chunk base)
    const __nv_bfloat16* Ag = A + (size_t)(bm + lrow) * KTOT + lch * 8;
    const __nv_bfloat16* Wg = W + (size_t)(bn + lrow) * KTOT + lch * 8;
    const uint32_t asw = smem_u32(&As[0][0]) + lrow * 80 + lch * 16;
    const uint32_t bsw = smem_u32(&Bs[0][0]) + lrow * 80 + lch * 16;
    const uint32_t bufstep = GTM * APITCH * 2;  // bytes per buffer

    float acc[2][8][4];
    #pragma unroll
    for (int mb = 0; mb < 2; mb++)
        #pragma unroll
        for (int nb = 0; nb < 8; nb++)
            #pragma unroll
            for (int i = 0; i < 4; i++) acc[mb][nb][i] = 0.f;

    // fragment smem addresses (per buffer 0)
    const uint32_t as0 = smem_u32(&As[0][0]);
    const uint32_t bs0 = smem_u32(&Bs[0][0]);
    // A frag: row = wm*32 + mb*16 + lane%16 ; col byte = (kk + 8*(lane/16))*2
    const uint32_t a_row = wm * 32 + (lane & 15);
    const uint32_t a_koff = (lane >> 4) * 16;       // bytes
    // B frag: row(n) = wn*64 + nb2*16 + lane%8 + 8*((lane>>4)&1); k = kk + 8*((lane>>3)&1)
    const uint32_t b_row = wn * 64 + (lane & 7) + 8 * ((lane >> 4) & 1);
    const uint32_t b_koff = ((lane >> 3) & 1) * 16; // bytes

    // prologue: stage 0 and 1
    #pragma unroll
    for (int st = 0; st < 2; st++) {
        #pragma unroll
        for (int j = 0; j < 2; j++) {
            CP_ASYNC16(asw + st * bufstep + j * 16, Ag + st * KB + j * 8);
            CP_ASYNC16(bsw + st * bufstep + j * 16, Wg + st * KB + j * 8);
        }
        CP_COMMIT();
    }

    for (int c = 0; c < NITER; c++) {
        const int buf = c & 1;
        CP_WAIT1();
        __syncthreads();

        const uint32_t ab = as0 + buf * bufstep;
        const uint32_t bb = bs0 + buf * bufstep;

        #pragma unroll
        for (int kk = 0; kk < 2; kk++) {           // two k16 halves
            uint32_t aF[2][4], bF[8][2];
            #pragma unroll
            for (int mb = 0; mb < 2; mb++) {
                uint32_t addr = ab + (a_row + mb * 16) * 80 + kk * 32 + a_koff;
                LDMATRIX_X4(aF[mb][0], aF[mb][1], aF[mb][2], aF[mb][3], addr);
            }
            #pragma unroll
            for (int nb2 = 0; nb2 < 4; nb2++) {
                uint32_t addr = bb + (b_row + nb2 * 16) * 80 + kk * 32 + b_koff;
                LDMATRIX_X4(bF[nb2 * 2][0], bF[nb2 * 2][1],
                            bF[nb2 * 2 + 1][0], bF[nb2 * 2 + 1][1], addr);
            }
            #pragma unroll
            for (int mb = 0; mb < 2; mb++)
                #pragma unroll
                for (int nb = 0; nb < 8; nb++)
                    MMA16816(acc[mb][nb][0], acc[mb][nb][1],
                             acc[mb][nb][2], acc[mb][nb][3],
                             aF[mb][0], aF[mb][1], aF[mb][2], aF[mb][3],
                             bF[nb][0], bF[nb][1]);
        }

        __syncthreads();
        if (c + 2 < NITER) {
            #pragma unroll
            for (int j = 0; j < 2; j++) {
                CP_ASYNC16(asw + buf * bufstep + j * 16, Ag + (c + 2) * KB + j * 8);
                CP_ASYNC16(bsw + buf * bufstep + j * 16, Wg + (c + 2) * KB + j * 8);
            }
        }
        CP_COMMIT();   // keep group count in lockstep even when empty
    }
    CP_WAIT0();

    // epilogue
    const int gr = lane >> 2;
    const int gc = (lane & 3) * 2;
    #pragma unroll
    for (int mb = 0; mb < 2; mb++) {
        const int row0 = bm + wm * 32 + mb * 16 + gr;
        #pragma unroll
        for (int nb = 0; nb < 8; nb++) {
            const int col = bn + wn * 64 + nb * 8 + gc;
            *(float2*)&C[(size_t)row0 * N + col] =
                make_float2(acc[mb][nb][0], acc[mb][nb][1]);
            *(float2*)&C[(size_t)(row0 + 8) * N + col] =
                make_float2(acc[mb][nb][2], acc[mb][nb][3]);
        }
    }
}

// ---------------------------------------------------------------------------
// Flash attention partials with ALiBi (fp32, online softmax), split-KV.
// ---------------------------------------------------------------------------
#define AROWS 64
#define STILE 64
#define CH 16
#define HHD 32
__global__ __launch_bounds__(128) void attn_partial_kernel(
    const float* __restrict__ q, const float* __restrict__ k,
    const float* __restrict__ v)
{
    __shared__ float Ks[STILE][HD_];
    __shared__ float Vs[STILE][HD_];

    const int hb   = blockIdx.z;
    const int b    = hb / H_;
    const int h    = hb % H_;
    const int split= blockIdx.y;
    const int wid  = threadIdx.x >> 5;
    const int lane = threadIdx.x & 31;
    const int r    = lane & 15;
    const int half = lane >> 4;

    const int t = blockIdx.x * AROWS + wid * 16 + r;
    const float slope = exp2f(-(float)(h + 1) / 16.0f);
    const float tf = (float)t;

    float qr[HHD];
    const float* qrow = q + ((size_t)(b * T_ + t)) * D_ + h * HD_ + half * HHD;
    #pragma unroll
    for (int i = 0; i < HHD / 4; i++) {
        float4 v4 = *(const float4*)(qrow + 4 * i);
        qr[4 * i + 0] = v4.x; qr[4 * i + 1] = v4.y;
        qr[4 * i + 2] = v4.z; qr[4 * i + 3] = v4.w;
    }

    float acc[HHD];
    #pragma unroll
    for (int d = 0; d < HHD; d++) acc[d] = 0.f;
    float m = -INFINITY, l = 0.f;

    const int sbeg = split * SPS;
    const int send = sbeg + SPS;

    for (int s0 = sbeg; s0 < send; s0 += STILE) {
        #pragma unroll
        for (int it = 0; it < 8; it++) {
            int idx = it * 128 + threadIdx.x;
            int rr = idx >> 4;
            int cc = (idx & 15) * 4;
            size_t gofs = ((size_t)(b * S_ + s0 + rr)) * D_ + h * HD_ + cc;
            *(float4*)&Ks[rr][cc] = *(const float4*)&k[gofs];
            *(float4*)&Vs[rr][cc] = *(const float4*)&v[gofs];
        }
        __syncthreads();

        #pragma unroll 1
        for (int c0 = 0; c0 < STILE; c0 += CH) {
            float sreg[CH];
            float tmax = -INFINITY;
            #pragma unroll
            for (int j = 0; j < CH; j++) {
                const int s = c0 + j;
                const float4* kr = (const float4*)&Ks[s][half * HHD];
                float sc = 0.f;
                #pragma unroll
                for (int i = 0; i < HHD / 4; i++) {
                    float4 kv = kr[i];
                    sc += qr[4 * i + 0] * kv.x + qr[4 * i + 1] * kv.y
                        + qr[4 * i + 2] * kv.z + qr[4 * i + 3] * kv.w;
                }
                sc += __shfl_xor_sync(0xffffffffu, sc, 16);
                sc = sc * SCALE_ - slope * fabsf(tf - (float)(s0 + s));
                sreg[j] = sc;
                tmax = fmaxf(tmax, sc);
            }

            float mnew = fmaxf(m, tmax);
            float corr = __expf(m - mnew);
            l *= corr;
            #pragma unroll
            for (int d = 0; d < HHD; d++) acc[d] *= corr;

            #pragma unroll
            for (int j = 0; j < CH; j++) {
                const int s = c0 + j;
                float p = __expf(sreg[j] - mnew);
                l += p;
                const float4* vr = (const float4*)&Vs[s][half * HHD];
                #pragma unroll
                for (int i = 0; i < HHD / 4; i++) {
                    float4 vv = vr[i];
                    acc[4 * i + 0] += p * vv.x;
                    acc[4 * i + 1] += p * vv.y;
                    acc[4 * i + 2] += p * vv.z;
                    acc[4 * i + 3] += p * vv.w;
                }
            }
            m = mnew;
        }
        __syncthreads();
    }

    const size_t pidx = (((size_t)split * B_ + b) * H_ + h) * T_ + t;
    float* pacc = g_pacc + pidx * HD_ + half * HHD;
    #pragma unroll
    for (int i = 0; i < HHD / 4; i++) {
        *(float4*)(pacc + 4 * i) =
            make_float4(acc[4 * i], acc[4 * i + 1], acc[4 * i + 2], acc[4 * i + 3]);
    }
    if (half == 0) {
        g_pm[pidx] = m;
        g_pl[pidx] = l;
    }
}

__global__ __launch_bounds__(256) void attn_combine_kernel(float* __restrict__ o)
{
    const int d = threadIdx.x & 63;
    const int rlocal = threadIdx.x >> 6;
    const size_t row = (size_t)blockIdx.x * 4 + rlocal;
    const int t = row % T_;
    const int h = (row / T_) % H_;
    const int b = row / ((size_t)T_ * H_);

    float m0 = g_pm[row];
    float l0 = g_pl[row];
    float m1 = g_pm[(size_t)B_ * H_ * T_ + row];
    float l1 = g_pl[(size_t)B_ * H_ * T_ + row];

    float M = fmaxf(m0, m1);
    float e0 = __expf(m0 - M), e1 = __expf(m1 - M);
    float L = l0 * e0 + l1 * e1;
    float inv = 1.f / L;

    float a0 = g_pacc[row * HD_ + d];
    float a1 = g_pacc[((size_t)B_ * H_ * T_ + row) * HD_ + d];
    float val = (a0 * e0 + a1 * e1) * inv;

    o[((size_t)(b * T_ + t)) * D_ + h * HD_ + d] = val;
}

// ---------------------------------------------------------------------------
// residual + RMSNorm
// ---------------------------------------------------------------------------
__global__ __launch_bounds__(256) void rms_kernel(
    const float* __restrict__ query, const float* __restrict__ proj,
    const float* __restrict__ w, float* __restrict__ out)
{
    __shared__ float sh[8];
    __shared__ float s_inv;
    const size_t row = blockIdx.x;
    const float* qr = query + row * D_;
    const float* pr = proj + row * D_;
    float* orow = out + row * D_;

    float x[4];
    float ss = 0.f;
    #pragma unroll
    for (int i = 0; i < 4; i++) {
        int idx = threadIdx.x + i * 256;
        x[i] = qr[idx] + pr[idx];
        ss += x[i] * x[i];
    }
    #pragma unroll
    for (int ofs = 16; ofs > 0; ofs >>= 1)
        ss += __shfl_xor_sync(0xffffffffu, ss, ofs);
    const int lane = threadIdx.x & 31, wid = threadIdx.x >> 5;
    if (lane == 0) sh[wid] = ss;
    __syncthreads();
    if (threadIdx.x == 0) {
        float tot = 0.f;
        #pragma unroll
        for (int i = 0; i < 8; i++) tot += sh[i];
        s_inv = rsqrtf(tot * (1.0f / D_) + RMS_EPS_);
    }
    __syncthreads();
    const float inv = s_inv;
    #pragma unroll
    for (int i = 0; i < 4; i++) {
        int idx = threadIdx.x + i * 256;
        orow[idx] = x[i] * inv * w[idx];
    }
}

// ---------------------------------------------------------------------------
extern "C" void kernel_launch(void* const* d_in, const int* in_sizes, int n_in,
                              void* d_out, int out_size)
{
    const float* query   = (const float*)d_in[0];
    const float* context = (const float*)d_in[1];
    const float* Wq      = (const float*)d_in[2];
    const float* Wk      = (const float*)d_in[3];
    const float* Wv      = (const float*)d_in[4];
    const float* Wo      = (const float*)d_in[5];
    const float* rmsw    = (const float*)d_in[6];
    float* out = (float*)d_out;

    float *pq, *pk, *pv, *patt, *pproj;
    cudaGetSymbolAddress((void**)&pq,    g_q);
    cudaGetSymbolAddress((void**)&pk,    g_k);
    cudaGetSymbolAddress((void**)&pv,    g_v);
    cudaGetSymbolAddress((void**)&patt,  g_att);
    cudaGetSymbolAddress((void**)&pproj, g_proj);

    __nv_bfloat16 *qs, *cs, *as, *wqs, *wks, *wvs, *wos;
    cudaGetSymbolAddress((void**)&qs,  g_qs);
    cudaGetSymbolAddress((void**)&cs,  g_cs);
    cudaGetSymbolAddress((void**)&as,  g_as);
    cudaGetSymbolAddress((void**)&wqs, g_wqs);
    cudaGetSymbolAddress((void**)&wks, g_wks);
    cudaGetSymbolAddress((void**)&wvs, g_wvs);
    cudaGetSymbolAddress((void**)&wos, g_wos);

    const int MQ = B_ * T_;   // 2048
    const int MK = B_ * S_;   // 4096

    // split conversions
    split_act<<<MQ, 256>>>(query, qs);
    split_act<<<MK, 256>>>(context, cs);
    split_wgt<<<D_, 256>>>(Wq, wqs);
    split_wgt<<<D_, 256>>>(Wk, wks);
    split_wgt<<<D_, 256>>>(Wv, wvs);
    split_wgt<<<D_, 256>>>(Wo, wos);

    // tensor-core projections (mma.sync)
    dim3 gq(D_ / GTN, MQ / GTM);   // 8 x 16
    dim3 gk(D_ / GTN, MK / GTM);   // 8 x 32
    gemm_bf16_mma<<<gq, 256>>>(qs, wqs, pq, D_);
    gemm_bf16_mma<<<gk, 256>>>(cs, wks, pk, D_);
    gemm_bf16_mma<<<gk, 256>>>(cs, wvs, pv, D_);

    // attention
    attn_partial_kernel<<<dim3(T_ / AROWS, NS_, B_ * H_), 128>>>(pq, pk, pv);
    attn_combine_kernel<<<(B_ * H_ * T_) / 4, 256>>>(patt);

    // output projection
    split_act<<<MQ, 256>>>(patt, as);
    gemm_bf16_mma<<<gq, 256>>>(as, wos, pproj, D_);

    rms_kernel<<<MQ, 256>>>(query, pproj, rmsw, out);
}

// round 9
// speedup vs baseline: 2.4384x; 1.4932x over previous
#include <cuda_runtime.h>
#include <cuda_bf16.h>
#include <math.h>
#include <stdint.h>

// Problem constants
#define B_  2
#define T_  1024
#define S_  2048
#define D_  1024
#define H_  16
#define HD_ 64
#define SCALE_ 0.125f
#define RMS_EPS_ 1e-6f

#define NS_ 2
#define SPS (S_ / NS_)

// bf16-split GEMM config
#define KTOT (3 * D_)
#define KB 32
#define NITER (KTOT / KB)
#define GTM 128
#define GTN 128
#define APITCH 40

// attention mma config
#define AM 64            // query rows per CTA (4 warps x 16)
#define AKE 192          // extended K dim (3 x 64)
#define APB 400          // smem row pitch bytes (200 bf16)

// Scratch (device globals; no allocation allowed)
__device__ float g_q[B_ * T_ * D_];
__device__ float g_k[B_ * S_ * D_];
__device__ float g_v[B_ * S_ * D_];
__device__ float g_att[B_ * T_ * D_];
__device__ float g_proj[B_ * T_ * D_];
__device__ float g_pacc[NS_ * B_ * H_ * T_ * HD_];
__device__ float g_pm[NS_ * B_ * H_ * T_];
__device__ float g_pl[NS_ * B_ * H_ * T_];
// bf16 split operands (projection GEMMs)
__device__ __nv_bfloat16 g_qs[(size_t)B_ * T_ * KTOT];
__device__ __nv_bfloat16 g_cs[(size_t)B_ * S_ * KTOT];
__device__ __nv_bfloat16 g_as[(size_t)B_ * T_ * KTOT];
__device__ __nv_bfloat16 g_wqs[(size_t)D_ * KTOT];
__device__ __nv_bfloat16 g_wks[(size_t)D_ * KTOT];
__device__ __nv_bfloat16 g_wvs[(size_t)D_ * KTOT];
__device__ __nv_bfloat16 g_wos[(size_t)D_ * KTOT];
// attention extended operands
__device__ __nv_bfloat16 g_qe[(size_t)B_ * H_ * T_ * AKE];        // [qhi|qhi|qlo]
__device__ __nv_bfloat16 g_ke[(size_t)B_ * H_ * S_ * AKE];        // [khi|klo|khi]
__device__ __nv_bfloat16 g_vte[(size_t)B_ * H_ * HD_ * 2 * S_];   // V^T [d][vhi(S)|vlo(S)]

// ============================ PTX helpers (base ISA) ========================
__device__ __forceinline__ uint32_t smem_u32(const void* p) {
    uint32_t a;
    asm("{ .reg .u64 t; cvta.to.shared.u64 t, %1; cvt.u32.u64 %0, t; }"
        : "=r"(a) : "l"(p));
    return a;
}

#define CP_ASYNC16(dst_u32, src_ptr) \
    asm volatile("cp.async.cg.shared.global [%0], [%1], 16;" \
        :: "r"(dst_u32), "l"(src_ptr))
#define CP_COMMIT() asm volatile("cp.async.commit_group;" ::: "memory")
#define CP_WAIT1()  asm volatile("cp.async.wait_group 1;" ::: "memory")
#define CP_WAIT0()  asm volatile("cp.async.wait_group 0;" ::: "memory")

#define LDMATRIX_X4(r0, r1, r2, r3, addr) \
    asm volatile("ldmatrix.sync.aligned.m8n8.x4.shared.b16 {%0,%1,%2,%3}, [%4];" \
        : "=r"(r0), "=r"(r1), "=r"(r2), "=r"(r3) : "r"(addr))

#define MMA16816(d0, d1, d2, d3, a0, a1, a2, a3, b0, b1) \
    asm volatile("mma.sync.aligned.m16n8k16.row.col.f32.bf16.bf16.f32 " \
        "{%0,%1,%2,%3}, {%4,%5,%6,%7}, {%8,%9}, {%0,%1,%2,%3};" \
        : "+f"(d0), "+f"(d1), "+f"(d2), "+f"(d3) \
        : "r"(a0), "r"(a1), "r"(a2), "r"(a3), "r"(b0), "r"(b1))

// pack two f32 -> bf16x2 (p0 -> low 16, p1 -> high 16)
__device__ __forceinline__ uint32_t pack_bf16x2(float p0, float p1) {
    uint32_t d;
    asm("cvt.rn.bf16x2.f32 %0, %1, %2;" : "=r"(d) : "f"(p1), "f"(p0));
    return d;
}
__device__ __forceinline__ float bf16lo_f(uint32_t u) {
    return __uint_as_float(u << 16);
}
__device__ __forceinline__ float bf16hi_f(uint32_t u) {
    return __uint_as_float(u & 0xffff0000u);
}

// ---------------------------------------------------------------------------
// Split conversion kernels (projection GEMM operands)
// ---------------------------------------------------------------------------
__global__ __launch_bounds__(256) void split_act(
    const float* __restrict__ in, __nv_bfloat16* __restrict__ out)
{
    const size_t row = blockIdx.x;
    const float* r = in + row * D_;
    __nv_bfloat16* o = out + row * (size_t)KTOT;
    #pragma unroll
    for (int i = 0; i < 4; i++) {
        int c = threadIdx.x + i * 256;
        float x = r[c];
        __nv_bfloat16 hi = __float2bfloat16(x);
        __nv_bfloat16 lo = __float2bfloat16(x - __bfloat162float(hi));
        o[c] = hi; o[D_ + c] = hi; o[2 * D_ + c] = lo;
    }
}

__global__ __launch_bounds__(256) void split_wgt(
    const float* __restrict__ in, __nv_bfloat16* __restrict__ out)
{
    const size_t row = blockIdx.x;
    const float* r = in + row * D_;
    __nv_bfloat16* o = out + row * (size_t)KTOT;
    #pragma unroll
    for (int i = 0; i < 4; i++) {
        int c = threadIdx.x + i * 256;
        float x = r[c];
        __nv_bfloat16 hi = __float2bfloat16(x);
        __nv_bfloat16 lo = __float2bfloat16(x - __bfloat162float(hi));
        o[c] = hi; o[D_ + c] = lo; o[2 * D_ + c] = hi;
    }
}

// ---------------------------------------------------------------------------
// Attention operand conversion:
//  qk_ext: fp32 [b][t][h*64+d] -> bf16 ext rows [(b*H+h)*L + t][192]
//          mode 0 (Q): [hi|hi|lo]    mode 1 (K): [hi|lo|hi]
// ---------------------------------------------------------------------------
__global__ __launch_bounds__(256) void qk_ext(
    const float* __restrict__ in, __nv_bfloat16* __restrict__ out,
    int L, int mode)
{
    const size_t row = blockIdx.x;        // b*L + t
    const int b = (int)(row / L);
    const int t = (int)(row % L);
    const float* r = in + row * D_;
    #pragma unroll
    for (int i = 0; i < 4; i++) {
        int d = threadIdx.x + i * 256;
        int h = d >> 6;
        int dd = d & 63;
        float x = r[d];
        __nv_bfloat16 hi = __float2bfloat16(x);
        __nv_bfloat16 lo = __float2bfloat16(x - __bfloat162float(hi));
        __nv_bfloat16* orow = out + ((size_t)(b * H_ + h) * L + t) * AKE;
        if (mode == 0) { orow[dd] = hi; orow[64 + dd] = hi; orow[128 + dd] = lo; }
        else           { orow[dd] = hi; orow[64 + dd] = lo; orow[128 + dd] = hi; }
    }
}

// v_ext_t: fp32 V [b][s][h*64+d] -> bf16 V^T rows [(b*H+h)*64 + d][2S] = [hi(s)|lo(s)]
// grid (S/32, 2, B*H), block (32, 8)
__global__ __launch_bounds__(256) void v_ext_t(
    const float* __restrict__ v, __nv_bfloat16* __restrict__ out)
{
    __shared__ float tile[32][33];
    const int s0 = blockIdx.x * 32;
    const int d0 = blockIdx.y * 32;
    const int bh = blockIdx.z;
    const int b = bh / H_;
    const int h = bh % H_;
    const int tx = threadIdx.x, ty = threadIdx.y;
    #pragma unroll
    for (int i = 0; i < 4; i++) {
        int s = s0 + ty + i * 8;
        tile[ty + i * 8][tx] = v[((size_t)(b * S_ + s)) * D_ + h * 64 + d0 + tx];
    }
    __syncthreads();
    #pragma unroll
    for (int i = 0; i < 4; i++) {
        int d = d0 + ty + i * 8;
        float x = tile[tx][ty + i * 8];
        __nv_bfloat16 hi = __float2bfloat16(x);
        __nv_bfloat16 lo = __float2bfloat16(x - __bfloat162float(hi));
        __nv_bfloat16* orow = out + ((size_t)(bh * 64 + d)) * (2 * S_);
        orow[s0 + tx] = hi;
        orow[S_ + s0 + tx] = lo;
    }
}

// ---------------------------------------------------------------------------
// bf16 mma.sync GEMM (unchanged from R8, validated)
// ---------------------------------------------------------------------------
__global__ __launch_bounds__(256) void gemm_bf16_mma(
    const __nv_bfloat16* __restrict__ A, const __nv_bfloat16* __restrict__ W,
    float* __restrict__ C, int N)
{
    __shared__ __align__(16) __nv_bfloat16 As[2][GTM * APITCH];
    __shared__ __align__(16) __nv_bfloat16 Bs[2][GTN * APITCH];

    const int tid = threadIdx.x;
    const int wid = tid >> 5;
    const int lane = tid & 31;
    const int wm = wid & 3;
    const int wn = wid >> 2;
    const int bm = blockIdx.y * GTM;
    const int bn = blockIdx.x * GTN;

    const int lrow = tid >> 1;
    const int lch  = (tid & 1) * 2;
    const __nv_bfloat16* Ag = A + (size_t)(bm + lrow) * KTOT + lch * 8;
    const __nv_bfloat16* Wg = W + (size_t)(bn + lrow) * KTOT + lch * 8;
    const uint32_t asw = smem_u32(&As[0][0]) + lrow * 80 + lch * 16;
    const uint32_t bsw = smem_u32(&Bs[0][0]) + lrow * 80 + lch * 16;
    const uint32_t bufstep = GTM * APITCH * 2;

    float acc[2][8][4];
    #pragma unroll
    for (int mb = 0; mb < 2; mb++)
        #pragma unroll
        for (int nb = 0; nb < 8; nb++)
            #pragma unroll
            for (int i = 0; i < 4; i++) acc[mb][nb][i] = 0.f;

    const uint32_t as0 = smem_u32(&As[0][0]);
    const uint32_t bs0 = smem_u32(&Bs[0][0]);
    const uint32_t a_row = wm * 32 + (lane & 15);
    const uint32_t a_koff = (lane >> 4) * 16;
    const uint32_t b_row = wn * 64 + (lane & 7) + 8 * ((lane >> 4) & 1);
    const uint32_t b_koff = ((lane >> 3) & 1) * 16;

    #pragma unroll
    for (int st = 0; st < 2; st++) {
        #pragma unroll
        for (int j = 0; j < 2; j++) {
            CP_ASYNC16(asw + st * bufstep + j * 16, Ag + st * KB + j * 8);
            CP_ASYNC16(bsw + st * bufstep + j * 16, Wg + st * KB + j * 8);
        }
        CP_COMMIT();
    }

    for (int c = 0; c < NITER; c++) {
        const int buf = c & 1;
        CP_WAIT1();
        __syncthreads();

        const uint32_t ab = as0 + buf * bufstep;
        const uint32_t bb = bs0 + buf * bufstep;

        #pragma unroll
        for (int kk = 0; kk < 2; kk++) {
            uint32_t aF[2][4], bF[8][2];
            #pragma unroll
            for (int mb = 0; mb < 2; mb++) {
                uint32_t addr = ab + (a_row + mb * 16) * 80 + kk * 32 + a_koff;
                LDMATRIX_X4(aF[mb][0], aF[mb][1], aF[mb][2], aF[mb][3], addr);
            }
            #pragma unroll
            for (int nb2 = 0; nb2 < 4; nb2++) {
                uint32_t addr = bb + (b_row + nb2 * 16) * 80 + kk * 32 + b_koff;
                LDMATRIX_X4(bF[nb2 * 2][0], bF[nb2 * 2][1],
                            bF[nb2 * 2 + 1][0], bF[nb2 * 2 + 1][1], addr);
            }
            #pragma unroll
            for (int mb = 0; mb < 2; mb++)
                #pragma unroll
                for (int nb = 0; nb < 8; nb++)
                    MMA16816(acc[mb][nb][0], acc[mb][nb][1],
                             acc[mb][nb][2], acc[mb][nb][3],
                             aF[mb][0], aF[mb][1], aF[mb][2], aF[mb][3],
                             bF[nb][0], bF[nb][1]);
        }

        __syncthreads();
        if (c + 2 < NITER) {
            #pragma unroll
            for (int j = 0; j < 2; j++) {
                CP_ASYNC16(asw + buf * bufstep + j * 16, Ag + (c + 2) * KB + j * 8);
                CP_ASYNC16(bsw + buf * bufstep + j * 16, Wg + (c + 2) * KB + j * 8);
            }
        }
        CP_COMMIT();
    }
    CP_WAIT0();

    const int gr = lane >> 2;
    const int gc = (lane & 3) * 2;
    #pragma unroll
    for (int mb = 0; mb < 2; mb++) {
        const int row0 = bm + wm * 32 + mb * 16 + gr;
        #pragma unroll
        for (int nb = 0; nb < 8; nb++) {
            const int col = bn + wn * 64 + nb * 8 + gc;
            *(float2*)&C[(size_t)row0 * N + col] =
                make_float2(acc[mb][nb][0], acc[mb][nb][1]);
            *(float2*)&C[(size_t)(row0 + 8) * N + col] =
                make_float2(acc[mb][nb][2], acc[mb][nb][3]);
        }
    }
}

// ---------------------------------------------------------------------------
// Tensor-core flash attention (split-KV partials, ALiBi, online softmax).
// CTA: 128 threads (4 warps x 16 query rows), S-tiles of 64.
// Q''*K''^T over k=192 (3-term bf16 split); P''*V'' over k=192.
// grid: (T/64, NS, B*H)
// ---------------------------------------------------------------------------
__global__ __launch_bounds__(128) void attn_mma(
    const __nv_bfloat16* __restrict__ qe,
    const __nv_bfloat16* __restrict__ ke,
    const __nv_bfloat16* __restrict__ vte)
{
    extern __shared__ char smraw[];
    const uint32_t sQ = smem_u32(smraw);
    const uint32_t sK = sQ + 64 * APB;
    const uint32_t sV = sK + 64 * APB;

    const int tid = threadIdx.x;
    const int wid = tid >> 5;
    const int lane = tid & 31;
    const int hb = blockIdx.z;             // b*H + h
    const int split = blockIdx.y;
    const int t0 = blockIdx.x * AM;
    const int h = hb % H_;

    const float slope = exp2f(-(float)(h + 1) / 16.0f);
    const size_t qrow0 = (size_t)hb * T_ + t0;
    const size_t krow0 = (size_t)hb * S_;
    const size_t vrow0 = (size_t)hb * 64;

    // Q tile (64 rows x 192) once
    for (int idx = tid; idx < 64 * 24; idx += 128) {
        int r = idx / 24, c = idx % 24;
        CP_ASYNC16(sQ + r * APB + c * 16, qe + (qrow0 + r) * AKE + c * 8);
    }
    CP_COMMIT();

    float sc[8][4], oF[8][4];
    #pragma unroll
    for (int nb = 0; nb < 8; nb++)
        #pragma unroll
        for (int i = 0; i < 4; i++) oF[nb][i] = 0.f;
    float m0 = -INFINITY, m1 = -INFINITY, l0 = 0.f, l1 = 0.f;

    const int r0 = lane >> 2;
    const float trow0 = (float)(t0 + wid * 16 + r0);
    const float trow1 = trow0 + 8.0f;

    // fragment addresses
    const uint32_t a_addr_base = sQ + (wid * 16 + (lane & 15)) * APB + (lane >> 4) * 16;
    const uint32_t b_row = (lane & 7) + 8 * ((lane >> 4) & 1);
    const uint32_t b_koff = ((lane >> 3) & 1) * 16;

    const int sbeg = split * SPS;
    const int send = sbeg + SPS;

    for (int s0 = sbeg; s0 < send; s0 += 64) {
        // load K and V^T tiles
        for (int idx = tid; idx < 64 * 24; idx += 128) {
            int r = idx / 24, c = idx % 24;
            CP_ASYNC16(sK + r * APB + c * 16, ke + (krow0 + s0 + r) * AKE + c * 8);
        }
        for (int idx = tid; idx < 64 * 24; idx += 128) {
            int r = idx / 24, c = idx % 24;
            const __nv_bfloat16* vb = vte + (vrow0 + r) * (size_t)(2 * S_);
            const __nv_bfloat16* src =
                (c < 8) ? vb + s0 + c * 8
                        : (c < 16 ? vb + S_ + s0 + (c - 8) * 8
                                  : vb + s0 + (c - 16) * 8);
            CP_ASYNC16(sV + r * APB + c * 16, src);
        }
        CP_COMMIT();
        CP_WAIT0();
        __syncthreads();

        // ----- QK: sc = Q'' * K''^T -----
        #pragma unroll
        for (int nb = 0; nb < 8; nb++)
            #pragma unroll
            for (int i = 0; i < 4; i++) sc[nb][i] = 0.f;

        #pragma unroll
        for (int ks = 0; ks < 12; ks++) {
            uint32_t aF[4], bF[8][2];
            LDMATRIX_X4(aF[0], aF[1], aF[2], aF[3], a_addr_base + ks * 32);
            #pragma unroll
            for (int nb2 = 0; nb2 < 4; nb2++) {
                uint32_t addr = sK + (b_row + nb2 * 16) * APB + ks * 32 + b_koff;
                LDMATRIX_X4(bF[nb2 * 2][0], bF[nb2 * 2][1],
                            bF[nb2 * 2 + 1][0], bF[nb2 * 2 + 1][1], addr);
            }
            #pragma unroll
            for (int nb = 0; nb < 8; nb++)
                MMA16816(sc[nb][0], sc[nb][1], sc[nb][2], sc[nb][3],
                         aF[0], aF[1], aF[2], aF[3], bF[nb][0], bF[nb][1]);
        }

        // ----- scale + ALiBi + row max -----
        float tm0 = -INFINITY, tm1 = -INFINITY;
        #pragma unroll
        for (int nb = 0; nb < 8; nb++) {
            float scol = (float)(s0 + nb * 8 + 2 * (lane & 3));
            sc[nb][0] = sc[nb][0] * SCALE_ - slope * fabsf(trow0 - scol);
            sc[nb][1] = sc[nb][1] * SCALE_ - slope * fabsf(trow0 - (scol + 1.f));
            sc[nb][2] = sc[nb][2] * SCALE_ - slope * fabsf(trow1 - scol);
            sc[nb][3] = sc[nb][3] * SCALE_ - slope * fabsf(trow1 - (scol + 1.f));
            tm0 = fmaxf(tm0, fmaxf(sc[nb][0], sc[nb][1]));
            tm1 = fmaxf(tm1, fmaxf(sc[nb][2], sc[nb][3]));
        }
        tm0 = fmaxf(tm0, __shfl_xor_sync(0xffffffffu, tm0, 1));
        tm0 = fmaxf(tm0, __shfl_xor_sync(0xffffffffu, tm0, 2));
        tm1 = fmaxf(tm1, __shfl_xor_sync(0xffffffffu, tm1, 1));
        tm1 = fmaxf(tm1, __shfl_xor_sync(0xffffffffu, tm1, 2));

        float mn0 = fmaxf(m0, tm0);
        float mn1 = fmaxf(m1, tm1);
        float cr0 = __expf(m0 - mn0);
        float cr1 = __expf(m1 - mn1);
        l0 *= cr0; l1 *= cr1;
        #pragma unroll
        for (int nb = 0; nb < 8; nb++) {
            oF[nb][0] *= cr0; oF[nb][1] *= cr0;
            oF[nb][2] *= cr1; oF[nb][3] *= cr1;
        }

        // ----- exp + row sums -----
        float rs0 = 0.f, rs1 = 0.f;
        #pragma unroll
        for (int nb = 0; nb < 8; nb++) {
            sc[nb][0] = __expf(sc[nb][0] - mn0);
            sc[nb][1] = __expf(sc[nb][1] - mn0);
            sc[nb][2] = __expf(sc[nb][2] - mn1);
            sc[nb][3] = __expf(sc[nb][3] - mn1);
            rs0 += sc[nb][0] + sc[nb][1];
            rs1 += sc[nb][2] + sc[nb][3];
        }
        rs0 += __shfl_xor_sync(0xffffffffu, rs0, 1);
        rs0 += __shfl_xor_sync(0xffffffffu, rs0, 2);
        rs1 += __shfl_xor_sync(0xffffffffu, rs1, 1);
        rs1 += __shfl_xor_sync(0xffffffffu, rs1, 2);
        l0 += rs0; l1 += rs1;
        m0 = mn0; m1 = mn1;

        // ----- pack phi A-fragments (C-frag -> A-frag reuse) -----
        uint32_t phi[4][4];
        #pragma unroll
        for (int ks = 0; ks < 4; ks++) {
            phi[ks][0] = pack_bf16x2(sc[2 * ks][0], sc[2 * ks][1]);
            phi[ks][1] = pack_bf16x2(sc[2 * ks][2], sc[2 * ks][3]);
            phi[ks][2] = pack_bf16x2(sc[2 * ks + 1][0], sc[2 * ks + 1][1]);
            phi[ks][3] = pack_bf16x2(sc[2 * ks + 1][2], sc[2 * ks + 1][3]);
        }

        // ----- PV: oF += P'' * V''  (k = [phi|phi|plo] x [vhi|vlo|vhi]) -----
        #pragma unroll
        for (int ks = 0; ks < 12; ks++) {
            uint32_t bF[8][2];
            #pragma unroll
            for (int nb2 = 0; nb2 < 4; nb2++) {
                uint32_t addr = sV + (b_row + nb2 * 16) * APB + ks * 32 + b_koff;
                LDMATRIX_X4(bF[nb2 * 2][0], bF[nb2 * 2][1],
                            bF[nb2 * 2 + 1][0], bF[nb2 * 2 + 1][1], addr);
            }
            uint32_t aP[4];
            if (ks < 8) {
                const int kk = ks & 3;
                aP[0] = phi[kk][0]; aP[1] = phi[kk][1];
                aP[2] = phi[kk][2]; aP[3] = phi[kk][3];
            } else {
                const int kk = ks - 8;
                #pragma unroll
                for (int j = 0; j < 4; j++) {
                    const int nb = 2 * kk + (j >> 1);
                    const int ci = (j & 1) * 2;
                    float pe = sc[nb][ci]     - bf16lo_f(phi[kk][j]);
                    float po = sc[nb][ci + 1] - bf16hi_f(phi[kk][j]);
                    aP[j] = pack_bf16x2(pe, po);
                }
            }
            #pragma unroll
            for (int nb = 0; nb < 8; nb++)
                MMA16816(oF[nb][0], oF[nb][1], oF[nb][2], oF[nb][3],
                         aP[0], aP[1], aP[2], aP[3], bF[nb][0], bF[nb][1]);
        }
        __syncthreads();
    }

    // epilogue: write raw partials + m,l
    const size_t base = (size_t)(split * B_ * H_ + hb) * T_;
    const size_t pidx0 = base + t0 + wid * 16 + r0;
    const size_t pidx1 = pidx0 + 8;
    #pragma unroll
    for (int nb = 0; nb < 8; nb++) {
        const int col = nb * 8 + 2 * (lane & 3);
        *(float2*)&g_pacc[pidx0 * HD_ + col] = make_float2(oF[nb][0], oF[nb][1]);
        *(float2*)&g_pacc[pidx1 * HD_ + col] = make_float2(oF[nb][2], oF[nb][3]);
    }
    if ((lane & 3) == 0) {
        g_pm[pidx0] = m0; g_pl[pidx0] = l0;
        g_pm[pidx1] = m1; g_pl[pidx1] = l1;
    }
}

// ---------------------------------------------------------------------------
// Combine split-KV partials -> [B,T,D]
// ---------------------------------------------------------------------------
__global__ __launch_bounds__(256) void attn_combine_kernel(float* __restrict__ o)
{
    const int d = threadIdx.x & 63;
    const int rlocal = threadIdx.x >> 6;
    const size_t row = (size_t)blockIdx.x * 4 + rlocal;
    const int t = row % T_;
    const int h = (row / T_) % H_;
    const int b = row / ((size_t)T_ * H_);

    float m0 = g_pm[row];
    float l0 = g_pl[row];
    float m1 = g_pm[(size_t)B_ * H_ * T_ + row];
    float l1 = g_pl[(size_t)B_ * H_ * T_ + row];

    float M = fmaxf(m0, m1);
    float e0 = __expf(m0 - M), e1 = __expf(m1 - M);
    float L = l0 * e0 + l1 * e1;
    float inv = 1.f / L;

    float a0 = g_pacc[row * HD_ + d];
    float a1 = g_pacc[((size_t)B_ * H_ * T_ + row) * HD_ + d];
    float val = (a0 * e0 + a1 * e1) * inv;

    o[((size_t)(b * T_ + t)) * D_ + h * HD_ + d] = val;
}

// ---------------------------------------------------------------------------
// residual + RMSNorm
// ---------------------------------------------------------------------------
__global__ __launch_bounds__(256) void rms_kernel(
    const float* __restrict__ query, const float* __restrict__ proj,
    const float* __restrict__ w, float* __restrict__ out)
{
    __shared__ float sh[8];
    __shared__ float s_inv;
    const size_t row = blockIdx.x;
    const float* qr = query + row * D_;
    const float* pr = proj + row * D_;
    float* orow = out + row * D_;

    float x[4];
    float ss = 0.f;
    #pragma unroll
    for (int i = 0; i < 4; i++) {
        int idx = threadIdx.x + i * 256;
        x[i] = qr[idx] + pr[idx];
        ss += x[i] * x[i];
    }
    #pragma unroll
    for (int ofs = 16; ofs > 0; ofs >>= 1)
        ss += __shfl_xor_sync(0xffffffffu, ss, ofs);
    const int lane = threadIdx.x & 31, wid = threadIdx.x >> 5;
    if (lane == 0) sh[wid] = ss;
    __syncthreads();
    if (threadIdx.x == 0) {
        float tot = 0.f;
        #pragma unroll
        for (int i = 0; i < 8; i++) tot += sh[i];
        s_inv = rsqrtf(tot * (1.0f / D_) + RMS_EPS_);
    }
    __syncthreads();
    const float inv = s_inv;
    #pragma unroll
    for (int i = 0; i < 4; i++) {
        int idx = threadIdx.x + i * 256;
        orow[idx] = x[i] * inv * w[idx];
    }
}

// ---------------------------------------------------------------------------
extern "C" void kernel_launch(void* const* d_in, const int* in_sizes, int n_in,
                              void* d_out, int out_size)
{
    const float* query   = (const float*)d_in[0];
    const float* context = (const float*)d_in[1];
    const float* Wq      = (const float*)d_in[2];
    const float* Wk      = (const float*)d_in[3];
    const float* Wv      = (const float*)d_in[4];
    const float* Wo      = (const float*)d_in[5];
    const float* rmsw    = (const float*)d_in[6];
    float* out = (float*)d_out;

    float *pq, *pk, *pv, *patt, *pproj;
    cudaGetSymbolAddress((void**)&pq,    g_q);
    cudaGetSymbolAddress((void**)&pk,    g_k);
    cudaGetSymbolAddress((void**)&pv,    g_v);
    cudaGetSymbolAddress((void**)&patt,  g_att);
    cudaGetSymbolAddress((void**)&pproj, g_proj);

    __nv_bfloat16 *qs, *cs, *as, *wqs, *wks, *wvs, *wos, *qe, *kke, *vte;
    cudaGetSymbolAddress((void**)&qs,  g_qs);
    cudaGetSymbolAddress((void**)&cs,  g_cs);
    cudaGetSymbolAddress((void**)&as,  g_as);
    cudaGetSymbolAddress((void**)&wqs, g_wqs);
    cudaGetSymbolAddress((void**)&wks, g_wks);
    cudaGetSymbolAddress((void**)&wvs, g_wvs);
    cudaGetSymbolAddress((void**)&wos, g_wos);
    cudaGetSymbolAddress((void**)&qe,  g_qe);
    cudaGetSymbolAddress((void**)&kke, g_ke);
    cudaGetSymbolAddress((void**)&vte, g_vte);

    static int smem_set = 0;
    if (!smem_set) {
        cudaFuncSetAttribute(attn_mma,
            cudaFuncAttributeMaxDynamicSharedMemorySize, 192 * APB);
        smem_set = 1;
    }

    const int MQ = B_ * T_;   // 2048
    const int MK = B_ * S_;   // 4096

    // split conversions for projection GEMMs
    split_act<<<MQ, 256>>>(query, qs);
    split_act<<<MK, 256>>>(context, cs);
    split_wgt<<<D_, 256>>>(Wq, wqs);
    split_wgt<<<D_, 256>>>(Wk, wks);
    split_wgt<<<D_, 256>>>(Wv, wvs);
    split_wgt<<<D_, 256>>>(Wo, wos);

    // projections
    dim3 gq(D_ / GTN, MQ / GTM);
    dim3 gk(D_ / GTN, MK / GTM);
    gemm_bf16_mma<<<gq, 256>>>(qs, wqs, pq, D_);
    gemm_bf16_mma<<<gk, 256>>>(cs, wks, pk, D_);
    gemm_bf16_mma<<<gk, 256>>>(cs, wvs, pv, D_);

    // attention operand conversion
    qk_ext<<<MQ, 256>>>(pq, qe, T_, 0);
    qk_ext<<<MK, 256>>>(pk, kke, S_, 1);
    v_ext_t<<<dim3(S_ / 32, 2, B_ * H_), dim3(32, 8)>>>(pv, vte);

    // tensor-core attention
    attn_mma<<<dim3(T_ / AM, NS_, B_ * H_), 128, 192 * APB>>>(qe, kke, vte);
    attn_combine_kernel<<<(B_ * H_ * T_) / 4, 256>>>(patt);

    // output projection
    split_act<<<MQ, 256>>>(patt, as);
    gemm_bf16_mma<<<gq, 256>>>(as, wos, pproj, D_);

    rms_kernel<<<MQ, 256>>>(query, pproj, rmsw, out);
}

// round 10
// speedup vs baseline: 2.5159x; 1.0318x over previous
#include <cuda_runtime.h>
#include <cuda_bf16.h>
#include <math.h>
#include <stdint.h>

// Problem constants
#define B_  2
#define T_  1024
#define S_  2048
#define D_  1024
#define H_  16
#define HD_ 64
#define SCALE_ 0.125f
#define RMS_EPS_ 1e-6f

#define NS_ 2
#define SPS (S_ / NS_)

// bf16-split GEMM config
#define KTOT (3 * D_)
#define KB2 64                    // bf16 K per stage
#define NITER2 (KTOT / KB2)       // 48
#define GTM 128
#define GTN 128
#define GPITCH 144                // smem row pitch bytes (64 bf16 + pad)
#define STAGE_BYTES (GTM * GPITCH)        // 18432 per array per stage
#define GEMM_SMEM (4 * STAGE_BYTES)       // A0 B0 A1 B1 = 73728

// attention mma config
#define AM 128           // query rows per CTA (8 warps x 16)
#define AKE 192          // extended K dim (3 x 64)
#define APB 400          // smem row pitch bytes
#define ATTN_SMEM ((AM + 64 + 64) * APB)  // Q + K + V = 102400

// Scratch (device globals; no allocation allowed)
__device__ float g_v[B_ * S_ * D_];
__device__ float g_proj[B_ * T_ * D_];
__device__ float g_pacc[NS_ * B_ * H_ * T_ * HD_];
__device__ float g_pm[NS_ * B_ * H_ * T_];
__device__ float g_pl[NS_ * B_ * H_ * T_];
// bf16 split operands (projection GEMMs)
__device__ __nv_bfloat16 g_qs[(size_t)B_ * T_ * KTOT];
__device__ __nv_bfloat16 g_cs[(size_t)B_ * S_ * KTOT];
__device__ __nv_bfloat16 g_as[(size_t)B_ * T_ * KTOT];
__device__ __nv_bfloat16 g_wqs[(size_t)D_ * KTOT];
__device__ __nv_bfloat16 g_wks[(size_t)D_ * KTOT];
__device__ __nv_bfloat16 g_wvs[(size_t)D_ * KTOT];
__device__ __nv_bfloat16 g_wos[(size_t)D_ * KTOT];
// attention extended operands
__device__ __nv_bfloat16 g_qe[(size_t)B_ * H_ * T_ * AKE];        // [qhi|qhi|qlo]
__device__ __nv_bfloat16 g_ke[(size_t)B_ * H_ * S_ * AKE];        // [khi|klo|khi]
__device__ __nv_bfloat16 g_vte[(size_t)B_ * H_ * HD_ * 2 * S_];   // V^T [d][vhi(S)|vlo(S)]

// ============================ PTX helpers (base ISA) ========================
__device__ __forceinline__ uint32_t smem_u32(const void* p) {
    uint32_t a;
    asm("{ .reg .u64 t; cvta.to.shared.u64 t, %1; cvt.u32.u64 %0, t; }"
        : "=r"(a) : "l"(p));
    return a;
}

#define CP_ASYNC16(dst_u32, src_ptr) \
    asm volatile("cp.async.cg.shared.global [%0], [%1], 16;" \
        :: "r"(dst_u32), "l"(src_ptr))
#define CP_COMMIT() asm volatile("cp.async.commit_group;" ::: "memory")
#define CP_WAIT1()  asm volatile("cp.async.wait_group 1;" ::: "memory")
#define CP_WAIT0()  asm volatile("cp.async.wait_group 0;" ::: "memory")

#define LDMATRIX_X4(r0, r1, r2, r3, addr) \
    asm volatile("ldmatrix.sync.aligned.m8n8.x4.shared.b16 {%0,%1,%2,%3}, [%4];" \
        : "=r"(r0), "=r"(r1), "=r"(r2), "=r"(r3) : "r"(addr))

#define MMA16816(d0, d1, d2, d3, a0, a1, a2, a3, b0, b1) \
    asm volatile("mma.sync.aligned.m16n8k16.row.col.f32.bf16.bf16.f32 " \
        "{%0,%1,%2,%3}, {%4,%5,%6,%7}, {%8,%9}, {%0,%1,%2,%3};" \
        : "+f"(d0), "+f"(d1), "+f"(d2), "+f"(d3) \
        : "r"(a0), "r"(a1), "r"(a2), "r"(a3), "r"(b0), "r"(b1))

__device__ __forceinline__ uint32_t pack_bf16x2(float p0, float p1) {
    uint32_t d;
    asm("cvt.rn.bf16x2.f32 %0, %1, %2;" : "=r"(d) : "f"(p1), "f"(p0));
    return d;
}
__device__ __forceinline__ float bf16lo_f(uint32_t u) {
    return __uint_as_float(u << 16);
}
__device__ __forceinline__ float bf16hi_f(uint32_t u) {
    return __uint_as_float(u & 0xffff0000u);
}

// ---------------------------------------------------------------------------
// Split conversion kernels (projection GEMM inputs)
// ---------------------------------------------------------------------------
__global__ __launch_bounds__(256) void split_act(
    const float* __restrict__ in, __nv_bfloat16* __restrict__ out)
{
    const size_t row = blockIdx.x;
    const float* r = in + row * D_;
    __nv_bfloat16* o = out + row * (size_t)KTOT;
    #pragma unroll
    for (int i = 0; i < 4; i++) {
        int c = threadIdx.x + i * 256;
        float x = r[c];
        __nv_bfloat16 hi = __float2bfloat16(x);
        __nv_bfloat16 lo = __float2bfloat16(x - __bfloat162float(hi));
        o[c] = hi; o[D_ + c] = hi; o[2 * D_ + c] = lo;
    }
}

__global__ __launch_bounds__(256) void split_wgt(
    const float* __restrict__ in, __nv_bfloat16* __restrict__ out)
{
    const size_t row = blockIdx.x;
    const float* r = in + row * D_;
    __nv_bfloat16* o = out + row * (size_t)KTOT;
    #pragma unroll
    for (int i = 0; i < 4; i++) {
        int c = threadIdx.x + i * 256;
        float x = r[c];
        __nv_bfloat16 hi = __float2bfloat16(x);
        __nv_bfloat16 lo = __float2bfloat16(x - __bfloat162float(hi));
        o[c] = hi; o[D_ + c] = lo; o[2 * D_ + c] = hi;
    }
}

// v_ext_t: fp32 V [b][s][h*64+d] -> bf16 V^T rows [(b*H+h)*64 + d][2S] = [hi(s)|lo(s)]
__global__ __launch_bounds__(256) void v_ext_t(
    const float* __restrict__ v, __nv_bfloat16* __restrict__ out)
{
    __shared__ float tile[32][33];
    const int s0 = blockIdx.x * 32;
    const int d0 = blockIdx.y * 32;
    const int bh = blockIdx.z;
    const int b = bh / H_;
    const int h = bh % H_;
    const int tx = threadIdx.x, ty = threadIdx.y;
    #pragma unroll
    for (int i = 0; i < 4; i++) {
        int s = s0 + ty + i * 8;
        tile[ty + i * 8][tx] = v[((size_t)(b * S_ + s)) * D_ + h * 64 + d0 + tx];
    }
    __syncthreads();
    #pragma unroll
    for (int i = 0; i < 4; i++) {
        int d = d0 + ty + i * 8;
        float x = tile[tx][ty + i * 8];
        __nv_bfloat16 hi = __float2bfloat16(x);
        __nv_bfloat16 lo = __float2bfloat16(x - __bfloat162float(hi));
        __nv_bfloat16* orow = out + ((size_t)(bh * 64 + d)) * (2 * S_);
        orow[s0 + tx] = hi;
        orow[S_ + s0 + tx] = lo;
    }
}

// ---------------------------------------------------------------------------
// bf16 mma.sync GEMM, KB=64 stage, dynamic smem, fused epilogues.
// emode 0: C fp32. emode 1: qe ext [hi|hi|lo]. emode 2: ke ext [hi|lo|hi].
// Lrows: rows per batch in M (for b,t decode in ext modes).
// ---------------------------------------------------------------------------
__global__ __launch_bounds__(256) void gemm_bf16_mma(
    const __nv_bfloat16* __restrict__ A, const __nv_bfloat16* __restrict__ W,
    float* __restrict__ C, __nv_bfloat16* __restrict__ eout,
    int N, int emode, int Lrows)
{
    extern __shared__ char gsm[];
    const uint32_t smb = smem_u32(gsm);

    const int tid = threadIdx.x;
    const int wid = tid >> 5;
    const int lane = tid & 31;
    const int wm = wid & 3;
    const int wn = wid >> 2;
    const int bm = blockIdx.y * GTM;
    const int bn = blockIdx.x * GTN;

    // loader: 2 threads per row, 4x16B chunks each
    const int lrow = tid >> 1;
    const int lhalf = tid & 1;
    const __nv_bfloat16* Ag = A + (size_t)(bm + lrow) * KTOT + lhalf * 32;
    const __nv_bfloat16* Wg = W + (size_t)(bn + lrow) * KTOT + lhalf * 32;
    const uint32_t lsm = lrow * GPITCH + lhalf * 64;

    float acc[2][8][4];
    #pragma unroll
    for (int mb = 0; mb < 2; mb++)
        #pragma unroll
        for (int nb = 0; nb < 8; nb++)
            #pragma unroll
            for (int i = 0; i < 4; i++) acc[mb][nb][i] = 0.f;

    const uint32_t a_row = wm * 32 + (lane & 15);
    const uint32_t a_koff = (lane >> 4) * 16;
    const uint32_t b_row = wn * 64 + (lane & 7) + 8 * ((lane >> 4) & 1);
    const uint32_t b_koff = ((lane >> 3) & 1) * 16;

    // prologue: stages 0,1
    #pragma unroll
    for (int st = 0; st < 2; st++) {
        const uint32_t ab = smb + st * 2 * STAGE_BYTES;
        #pragma unroll
        for (int j = 0; j < 4; j++) {
            CP_ASYNC16(ab + lsm + j * 16, Ag + st * KB2 + j * 8);
            CP_ASYNC16(ab + STAGE_BYTES + lsm + j * 16, Wg + st * KB2 + j * 8);
        }
        CP_COMMIT();
    }

    for (int c = 0; c < NITER2; c++) {
        const int buf = c & 1;
        CP_WAIT1();
        __syncthreads();

        const uint32_t ab = smb + buf * 2 * STAGE_BYTES;
        const uint32_t bb = ab + STAGE_BYTES;

        #pragma unroll
        for (int kk = 0; kk < 4; kk++) {
            uint32_t aF[2][4], bF[8][2];
            #pragma unroll
            for (int mb = 0; mb < 2; mb++) {
                uint32_t addr = ab + (a_row + mb * 16) * GPITCH + kk * 32 + a_koff;
                LDMATRIX_X4(aF[mb][0], aF[mb][1], aF[mb][2], aF[mb][3], addr);
            }
            #pragma unroll
            for (int nb2 = 0; nb2 < 4; nb2++) {
                uint32_t addr = bb + (b_row + nb2 * 16) * GPITCH + kk * 32 + b_koff;
                LDMATRIX_X4(bF[nb2 * 2][0], bF[nb2 * 2][1],
                            bF[nb2 * 2 + 1][0], bF[nb2 * 2 + 1][1], addr);
            }
            #pragma unroll
            for (int mb = 0; mb < 2; mb++)
                #pragma unroll
                for (int nb = 0; nb < 8; nb++)
                    MMA16816(acc[mb][nb][0], acc[mb][nb][1],
                             acc[mb][nb][2], acc[mb][nb][3],
                             aF[mb][0], aF[mb][1], aF[mb][2], aF[mb][3],
                             bF[nb][0], bF[nb][1]);
        }

        __syncthreads();
        if (c + 2 < NITER2) {
            const uint32_t pb = smb + buf * 2 * STAGE_BYTES;
            #pragma unroll
            for (int j = 0; j < 4; j++) {
                CP_ASYNC16(pb + lsm + j * 16, Ag + (c + 2) * KB2 + j * 8);
                CP_ASYNC16(pb + STAGE_BYTES + lsm + j * 16, Wg + (c + 2) * KB2 + j * 8);
            }
        }
        CP_COMMIT();
    }
    CP_WAIT0();

    const int gr = lane >> 2;
    const int gc = (lane & 3) * 2;

    if (emode == 0) {
        #pragma unroll
        for (int mb = 0; mb < 2; mb++) {
            const int row0 = bm + wm * 32 + mb * 16 + gr;
            #pragma unroll
            for (int nb = 0; nb < 8; nb++) {
                const int col = bn + wn * 64 + nb * 8 + gc;
                *(float2*)&C[(size_t)row0 * N + col] =
                    make_float2(acc[mb][nb][0], acc[mb][nb][1]);
                *(float2*)&C[(size_t)(row0 + 8) * N + col] =
                    make_float2(acc[mb][nb][2], acc[mb][nb][3]);
            }
        }
    } else {
        #pragma unroll
        for (int mb = 0; mb < 2; mb++) {
            #pragma unroll
            for (int half = 0; half < 2; half++) {
                const int row = bm + wm * 32 + mb * 16 + gr + half * 8;
                const int b = row / Lrows;
                const int t = row % Lrows;
                #pragma unroll
                for (int nb = 0; nb < 8; nb++) {
                    const int col = bn + wn * 64 + nb * 8 + gc;
                    const int h = col >> 6;
                    const int dd = col & 63;
                    float x0 = acc[mb][nb][half * 2];
                    float x1 = acc[mb][nb][half * 2 + 1];
                    __nv_bfloat16 h0 = __float2bfloat16(x0);
                    __nv_bfloat16 h1 = __float2bfloat16(x1);
                    __nv_bfloat16 l0 = __float2bfloat16(x0 - __bfloat162float(h0));
                    __nv_bfloat16 l1 = __float2bfloat16(x1 - __bfloat162float(h1));
                    __nv_bfloat16* orow =
                        eout + ((size_t)(b * H_ + h) * Lrows + t) * AKE;
                    __nv_bfloat162 hv; hv.x = h0; hv.y = h1;
                    __nv_bfloat162 lv; lv.x = l0; lv.y = l1;
                    if (emode == 1) {
                        *(__nv_bfloat162*)&orow[dd] = hv;
                        *(__nv_bfloat162*)&orow[64 + dd] = hv;
                        *(__nv_bfloat162*)&orow[128 + dd] = lv;
                    } else {
                        *(__nv_bfloat162*)&orow[dd] = hv;
                        *(__nv_bfloat162*)&orow[64 + dd] = lv;
                        *(__nv_bfloat162*)&orow[128 + dd] = hv;
                    }
                }
            }
        }
    }
}

// ---------------------------------------------------------------------------
// Tensor-core flash attention (split-KV partials, ALiBi, online softmax).
// CTA: 256 threads (8 warps x 16 query rows = 128 rows), S-tiles of 64.
// grid: (T/128, NS, B*H)
// ---------------------------------------------------------------------------
__global__ __launch_bounds__(256) void attn_mma(
    const __nv_bfloat16* __restrict__ qe,
    const __nv_bfloat16* __restrict__ ke,
    const __nv_bfloat16* __restrict__ vte)
{
    extern __shared__ char smraw[];
    const uint32_t sQ = smem_u32(smraw);
    const uint32_t sK = sQ + AM * APB;
    const uint32_t sV = sK + 64 * APB;

    const int tid = threadIdx.x;
    const int wid = tid >> 5;
    const int lane = tid & 31;
    const int hb = blockIdx.z;
    const int split = blockIdx.y;
    const int t0 = blockIdx.x * AM;
    const int h = hb % H_;

    const float slope = exp2f(-(float)(h + 1) / 16.0f);
    const size_t qrow0 = (size_t)hb * T_ + t0;
    const size_t krow0 = (size_t)hb * S_;
    const size_t vrow0 = (size_t)hb * 64;

    // Q tile (128 rows x 192)
    for (int idx = tid; idx < AM * 24; idx += 256) {
        int r = idx / 24, c = idx % 24;
        CP_ASYNC16(sQ + r * APB + c * 16, qe + (qrow0 + r) * AKE + c * 8);
    }
    CP_COMMIT();

    float sc[8][4], oF[8][4];
    #pragma unroll
    for (int nb = 0; nb < 8; nb++)
        #pragma unroll
        for (int i = 0; i < 4; i++) oF[nb][i] = 0.f;
    float m0 = -INFINITY, m1 = -INFINITY, l0 = 0.f, l1 = 0.f;

    const int r0 = lane >> 2;
    const float trow0 = (float)(t0 + wid * 16 + r0);
    const float trow1 = trow0 + 8.0f;

    const uint32_t a_addr_base = sQ + (wid * 16 + (lane & 15)) * APB + (lane >> 4) * 16;
    const uint32_t b_row = (lane & 7) + 8 * ((lane >> 4) & 1);
    const uint32_t b_koff = ((lane >> 3) & 1) * 16;

    const int sbeg = split * SPS;
    const int send = sbeg + SPS;

    for (int s0 = sbeg; s0 < send; s0 += 64) {
        for (int idx = tid; idx < 64 * 24; idx += 256) {
            int r = idx / 24, c = idx % 24;
            CP_ASYNC16(sK + r * APB + c * 16, ke + (krow0 + s0 + r) * AKE + c * 8);
        }
        for (int idx = tid; idx < 64 * 24; idx += 256) {
            int r = idx / 24, c = idx % 24;
            const __nv_bfloat16* vb = vte + (vrow0 + r) * (size_t)(2 * S_);
            const __nv_bfloat16* src =
                (c < 8) ? vb + s0 + c * 8
                        : (c < 16 ? vb + S_ + s0 + (c - 8) * 8
                                  : vb + s0 + (c - 16) * 8);
            CP_ASYNC16(sV + r * APB + c * 16, src);
        }
        CP_COMMIT();
        CP_WAIT0();
        __syncthreads();

        // ----- QK -----
        #pragma unroll
        for (int nb = 0; nb < 8; nb++)
            #pragma unroll
            for (int i = 0; i < 4; i++) sc[nb][i] = 0.f;

        #pragma unroll
        for (int ks = 0; ks < 12; ks++) {
            uint32_t aF[4], bF[8][2];
            LDMATRIX_X4(aF[0], aF[1], aF[2], aF[3], a_addr_base + ks * 32);
            #pragma unroll
            for (int nb2 = 0; nb2 < 4; nb2++) {
                uint32_t addr = sK + (b_row + nb2 * 16) * APB + ks * 32 + b_koff;
                LDMATRIX_X4(bF[nb2 * 2][0], bF[nb2 * 2][1],
                            bF[nb2 * 2 + 1][0], bF[nb2 * 2 + 1][1], addr);
            }
            #pragma unroll
            for (int nb = 0; nb < 8; nb++)
                MMA16816(sc[nb][0], sc[nb][1], sc[nb][2], sc[nb][3],
                         aF[0], aF[1], aF[2], aF[3], bF[nb][0], bF[nb][1]);
        }

        // ----- scale + ALiBi + row max -----
        float tm0 = -INFINITY, tm1 = -INFINITY;
        #pragma unroll
        for (int nb = 0; nb < 8; nb++) {
            float scol = (float)(s0 + nb * 8 + 2 * (lane & 3));
            sc[nb][0] = sc[nb][0] * SCALE_ - slope * fabsf(trow0 - scol);
            sc[nb][1] = sc[nb][1] * SCALE_ - slope * fabsf(trow0 - (scol + 1.f));
            sc[nb][2] = sc[nb][2] * SCALE_ - slope * fabsf(trow1 - scol);
            sc[nb][3] = sc[nb][3] * SCALE_ - slope * fabsf(trow1 - (scol + 1.f));
            tm0 = fmaxf(tm0, fmaxf(sc[nb][0], sc[nb][1]));
            tm1 = fmaxf(tm1, fmaxf(sc[nb][2], sc[nb][3]));
        }
        tm0 = fmaxf(tm0, __shfl_xor_sync(0xffffffffu, tm0, 1));
        tm0 = fmaxf(tm0, __shfl_xor_sync(0xffffffffu, tm0, 2));
        tm1 = fmaxf(tm1, __shfl_xor_sync(0xffffffffu, tm1, 1));
        tm1 = fmaxf(tm1, __shfl_xor_sync(0xffffffffu, tm1, 2));

        float mn0 = fmaxf(m0, tm0);
        float mn1 = fmaxf(m1, tm1);
        float cr0 = __expf(m0 - mn0);
        float cr1 = __expf(m1 - mn1);
        l0 *= cr0; l1 *= cr1;
        #pragma unroll
        for (int nb = 0; nb < 8; nb++) {
            oF[nb][0] *= cr0; oF[nb][1] *= cr0;
            oF[nb][2] *= cr1; oF[nb][3] *= cr1;
        }

        // ----- exp + row sums -----
        float rs0 = 0.f, rs1 = 0.f;
        #pragma unroll
        for (int nb = 0; nb < 8; nb++) {
            sc[nb][0] = __expf(sc[nb][0] - mn0);
            sc[nb][1] = __expf(sc[nb][1] - mn0);
            sc[nb][2] = __expf(sc[nb][2] - mn1);
            sc[nb][3] = __expf(sc[nb][3] - mn1);
            rs0 += sc[nb][0] + sc[nb][1];
            rs1 += sc[nb][2] + sc[nb][3];
        }
        rs0 += __shfl_xor_sync(0xffffffffu, rs0, 1);
        rs0 += __shfl_xor_sync(0xffffffffu, rs0, 2);
        rs1 += __shfl_xor_sync(0xffffffffu, rs1, 1);
        rs1 += __shfl_xor_sync(0xffffffffu, rs1, 2);
        l0 += rs0; l1 += rs1;
        m0 = mn0; m1 = mn1;

        // ----- pack phi A-fragments -----
        uint32_t phi[4][4];
        #pragma unroll
        for (int ks = 0; ks < 4; ks++) {
            phi[ks][0] = pack_bf16x2(sc[2 * ks][0], sc[2 * ks][1]);
            phi[ks][1] = pack_bf16x2(sc[2 * ks][2], sc[2 * ks][3]);
            phi[ks][2] = pack_bf16x2(sc[2 * ks + 1][0], sc[2 * ks + 1][1]);
            phi[ks][3] = pack_bf16x2(sc[2 * ks + 1][2], sc[2 * ks + 1][3]);
        }

        // ----- PV -----
        #pragma unroll
        for (int ks = 0; ks < 12; ks++) {
            uint32_t bF[8][2];
            #pragma unroll
            for (int nb2 = 0; nb2 < 4; nb2++) {
                uint32_t addr = sV + (b_row + nb2 * 16) * APB + ks * 32 + b_koff;
                LDMATRIX_X4(bF[nb2 * 2][0], bF[nb2 * 2][1],
                            bF[nb2 * 2 + 1][0], bF[nb2 * 2 + 1][1], addr);
            }
            uint32_t aP[4];
            if (ks < 8) {
                const int kk = ks & 3;
                aP[0] = phi[kk][0]; aP[1] = phi[kk][1];
                aP[2] = phi[kk][2]; aP[3] = phi[kk][3];
            } else {
                const int kk = ks - 8;
                #pragma unroll
                for (int j = 0; j < 4; j++) {
                    const int nb = 2 * kk + (j >> 1);
                    const int ci = (j & 1) * 2;
                    float pe = sc[nb][ci]     - bf16lo_f(phi[kk][j]);
                    float po = sc[nb][ci + 1] - bf16hi_f(phi[kk][j]);
                    aP[j] = pack_bf16x2(pe, po);
                }
            }
            #pragma unroll
            for (int nb = 0; nb < 8; nb++)
                MMA16816(oF[nb][0], oF[nb][1], oF[nb][2], oF[nb][3],
                         aP[0], aP[1], aP[2], aP[3], bF[nb][0], bF[nb][1]);
        }
        __syncthreads();
    }

    // epilogue: write raw partials + m,l
    const size_t base = (size_t)(split * B_ * H_ + hb) * T_;
    const size_t pidx0 = base + t0 + wid * 16 + r0;
    const size_t pidx1 = pidx0 + 8;
    #pragma unroll
    for (int nb = 0; nb < 8; nb++) {
        const int col = nb * 8 + 2 * (lane & 3);
        *(float2*)&g_pacc[pidx0 * HD_ + col] = make_float2(oF[nb][0], oF[nb][1]);
        *(float2*)&g_pacc[pidx1 * HD_ + col] = make_float2(oF[nb][2], oF[nb][3]);
    }
    if ((lane & 3) == 0) {
        g_pm[pidx0] = m0; g_pl[pidx0] = l0;
        g_pm[pidx1] = m1; g_pl[pidx1] = l1;
    }
}

// ---------------------------------------------------------------------------
// Combine split-KV partials -> split-act layout [b*T+t][hi|hi|lo] (g_as)
// ---------------------------------------------------------------------------
__global__ __launch_bounds__(256) void attn_combine_kernel(
    __nv_bfloat16* __restrict__ as_out)
{
    const int d = threadIdx.x & 63;
    const int rlocal = threadIdx.x >> 6;
    const size_t row = (size_t)blockIdx.x * 4 + rlocal;
    const int t = row % T_;
    const int h = (row / T_) % H_;
    const int b = row / ((size_t)T_ * H_);

    float m0 = g_pm[row];
    float l0 = g_pl[row];
    float m1 = g_pm[(size_t)B_ * H_ * T_ + row];
    float l1 = g_pl[(size_t)B_ * H_ * T_ + row];

    float M = fmaxf(m0, m1);
    float e0 = __expf(m0 - M), e1 = __expf(m1 - M);
    float L = l0 * e0 + l1 * e1;
    float inv = 1.f / L;

    float a0 = g_pacc[row * HD_ + d];
    float a1 = g_pacc[((size_t)B_ * H_ * T_ + row) * HD_ + d];
    float val = (a0 * e0 + a1 * e1) * inv;

    __nv_bfloat16 hi = __float2bfloat16(val);
    __nv_bfloat16 lo = __float2bfloat16(val - __bfloat162float(hi));
    const int c = h * 64 + d;
    __nv_bfloat16* orow = as_out + ((size_t)(b * T_ + t)) * KTOT;
    orow[c] = hi; orow[D_ + c] = hi; orow[2 * D_ + c] = lo;
}

// ---------------------------------------------------------------------------
// residual + RMSNorm
// ---------------------------------------------------------------------------
__global__ __launch_bounds__(256) void rms_kernel(
    const float* __restrict__ query, const float* __restrict__ proj,
    const float* __restrict__ w, float* __restrict__ out)
{
    __shared__ float sh[8];
    __shared__ float s_inv;
    const size_t row = blockIdx.x;
    const float* qr = query + row * D_;
    const float* pr = proj + row * D_;
    float* orow = out + row * D_;

    float x[4];
    float ss = 0.f;
    #pragma unroll
    for (int i = 0; i < 4; i++) {
        int idx = threadIdx.x + i * 256;
        x[i] = qr[idx] + pr[idx];
        ss += x[i] * x[i];
    }
    #pragma unroll
    for (int ofs = 16; ofs > 0; ofs >>= 1)
        ss += __shfl_xor_sync(0xffffffffu, ss, ofs);
    const int lane = threadIdx.x & 31, wid = threadIdx.x >> 5;
    if (lane == 0) sh[wid] = ss;
    __syncthreads();
    if (threadIdx.x == 0) {
        float tot = 0.f;
        #pragma unroll
        for (int i = 0; i < 8; i++) tot += sh[i];
        s_inv = rsqrtf(tot * (1.0f / D_) + RMS_EPS_);
    }
    __syncthreads();
    const float inv = s_inv;
    #pragma unroll
    for (int i = 0; i < 4; i++) {
        int idx = threadIdx.x + i * 256;
        orow[idx] = x[i] * inv * w[idx];
    }
}

// ---------------------------------------------------------------------------
extern "C" void kernel_launch(void* const* d_in, const int* in_sizes, int n_in,
                              void* d_out, int out_size)
{
    const float* query   = (const float*)d_in[0];
    const float* context = (const float*)d_in[1];
    const float* Wq      = (const float*)d_in[2];
    const float* Wk      = (const float*)d_in[3];
    const float* Wv      = (const float*)d_in[4];
    const float* Wo      = (const float*)d_in[5];
    const float* rmsw    = (const float*)d_in[6];
    float* out = (float*)d_out;

    float *pv, *pproj;
    cudaGetSymbolAddress((void**)&pv,    g_v);
    cudaGetSymbolAddress((void**)&pproj, g_proj);

    __nv_bfloat16 *qs, *cs, *as, *wqs, *wks, *wvs, *wos, *qe, *kke, *vte;
    cudaGetSymbolAddress((void**)&qs,  g_qs);
    cudaGetSymbolAddress((void**)&cs,  g_cs);
    cudaGetSymbolAddress((void**)&as,  g_as);
    cudaGetSymbolAddress((void**)&wqs, g_wqs);
    cudaGetSymbolAddress((void**)&wks, g_wks);
    cudaGetSymbolAddress((void**)&wvs, g_wvs);
    cudaGetSymbolAddress((void**)&wos, g_wos);
    cudaGetSymbolAddress((void**)&qe,  g_qe);
    cudaGetSymbolAddress((void**)&kke, g_ke);
    cudaGetSymbolAddress((void**)&vte, g_vte);

    cudaFuncSetAttribute(gemm_bf16_mma,
        cudaFuncAttributeMaxDynamicSharedMemorySize, GEMM_SMEM);
    cudaFuncSetAttribute(attn_mma,
        cudaFuncAttributeMaxDynamicSharedMemorySize, ATTN_SMEM);

    const int MQ = B_ * T_;   // 2048
    const int MK = B_ * S_;   // 4096

    // split conversions for projection GEMM inputs
    split_act<<<MQ, 256>>>(query, qs);
    split_act<<<MK, 256>>>(context, cs);
    split_wgt<<<D_, 256>>>(Wq, wqs);
    split_wgt<<<D_, 256>>>(Wk, wks);
    split_wgt<<<D_, 256>>>(Wv, wvs);
    split_wgt<<<D_, 256>>>(Wo, wos);

    // projections (Q/K fused into attention-ext epilogues; V to fp32)
    dim3 gq(D_ / GTN, MQ / GTM);
    dim3 gk(D_ / GTN, MK / GTM);
    gemm_bf16_mma<<<gq, 256, GEMM_SMEM>>>(qs, wqs, nullptr, qe,  D_, 1, T_);
    gemm_bf16_mma<<<gk, 256, GEMM_SMEM>>>(cs, wks, nullptr, kke, D_, 2, S_);
    gemm_bf16_mma<<<gk, 256, GEMM_SMEM>>>(cs, wvs, pv, nullptr,  D_, 0, 0);

    v_ext_t<<<dim3(S_ / 32, 2, B_ * H_), dim3(32, 8)>>>(pv, vte);

    // tensor-core attention
    attn_mma<<<dim3(T_ / AM, NS_, B_ * H_), 256, ATTN_SMEM>>>(qe, kke, vte);
    attn_combine_kernel<<<(B_ * H_ * T_) / 4, 256>>>(as);

    // output projection
    gemm_bf16_mma<<<gq, 256, GEMM_SMEM>>>(as, wos, pproj, nullptr, D_, 0, 0);

    rms_kernel<<<MQ, 256>>>(query, pproj, rmsw, out);
}